// round 1
// baseline (speedup 1.0000x reference)
#include <cuda_runtime.h>
#include <cuda_bf16.h>
#include <math.h>

// Shapes (fixed by the problem)
#define NB   32
#define DIM  256
#define DI   128
#define HW   4096   // 64*64
#define CNT  (NB*HW)  // BN count per channel = 131072

// ---------------- device scratch (no allocations allowed) ----------------
__device__ float d_xsum[NB*DIM];          // per (n,c) sum over HW of x
__device__ float d_tp[NB*DI*DI];          // softmax(theta_s outer phi_s)
__device__ float d_tb[NB*DI];             // theta_phi @ b_g
__device__ float d_T[NB*DI*DIM];          // theta_phi @ w_g
__device__ float d_W2[NB*DIM*DIM];        // w_out @ T
__device__ float d_biasp[NB*DIM];         // w_out @ tb + b_out
__device__ float d_p[(size_t)NB*DIM*HW];  // pre-BN output (134 MB)
__device__ float d_chsum[DIM];
__device__ float d_chsumsq[DIM];
__device__ float d_scale[DIM];
__device__ float d_shift[DIM];

// ---------------- K0: zero BN accumulators ----------------
__global__ void zero_stats_kernel() {
    int t = threadIdx.x;
    d_chsum[t] = 0.f;
    d_chsumsq[t] = 0.f;
}

// ---------------- K1: per-(n,c) channel sums of x ----------------
// grid = NB*DIM blocks, 256 threads, each block sums 4096 contiguous floats
__global__ void xsum_kernel(const float* __restrict__ x) {
    const float4* src = (const float4*)x + (size_t)blockIdx.x * 1024;
    float s = 0.f;
#pragma unroll
    for (int it = 0; it < 4; ++it) {
        float4 v = src[it * 256 + threadIdx.x];
        s += v.x + v.y + v.z + v.w;
    }
#pragma unroll
    for (int o = 16; o; o >>= 1) s += __shfl_down_sync(0xffffffffu, s, o);
    __shared__ float ws[8];
    if ((threadIdx.x & 31) == 0) ws[threadIdx.x >> 5] = s;
    __syncthreads();
    if (threadIdx.x < 8) {
        s = ws[threadIdx.x];
#pragma unroll
        for (int o = 4; o; o >>= 1) s += __shfl_down_sync(0xffu, s, o);
        if (threadIdx.x == 0) d_xsum[blockIdx.x] = s;
    }
}

// ---------------- K2: theta_s, phi_s, softmax(theta_phi), tb ----------------
// grid = NB blocks, 128 threads (thread i owns row i)
__global__ void attn_kernel(const float* __restrict__ w_theta,
                            const float* __restrict__ b_theta,
                            const float* __restrict__ w_phi,
                            const float* __restrict__ b_phi,
                            const float* __restrict__ b_g) {
    const int n = blockIdx.x;
    const int i = threadIdx.x;
    __shared__ float xs[DIM];
    __shared__ float ts[DI];
    __shared__ float ps[DI];
    xs[i]        = d_xsum[n * DIM + i];
    xs[i + 128]  = d_xsum[n * DIM + 128 + i];
    __syncthreads();

    float dt = 0.f, dp = 0.f;
    const float* wt = w_theta + (size_t)i * DIM;
    const float* wp = w_phi   + (size_t)i * DIM;
#pragma unroll 4
    for (int k = 0; k < DIM; ++k) {
        float xv = xs[k];
        dt = fmaf(wt[k], xv, dt);
        dp = fmaf(wp[k], xv, dp);
    }
    // sum over 256 pooled positions: sum_p xp = xsum/16, bias appears 256 times
    ts[i] = dt * (1.f / 16.f) + 256.f * b_theta[i];
    ps[i] = dp * (1.f / 16.f) + 256.f * b_phi[i];
    __syncthreads();

    const float sc = 0.08838834764831845f; // 128^-0.5
    float a = ts[i] * sc;
    float m = -1e30f;
#pragma unroll 4
    for (int j = 0; j < DI; ++j) m = fmaxf(m, a * ps[j]);
    float sum = 0.f;
#pragma unroll 4
    for (int j = 0; j < DI; ++j) sum += expf(a * ps[j] - m);
    float inv = 1.f / sum;

    float tbacc = 0.f;
    float* row = d_tp + ((size_t)n * DI + i) * DI;
#pragma unroll 4
    for (int j = 0; j < DI; ++j) {
        float e = expf(a * ps[j] - m) * inv;
        row[j] = e;
        tbacc = fmaf(e, b_g[j], tbacc);
    }
    d_tb[n * DI + i] = tbacc;
}

// ---------------- generic batched SGEMM: C = A@B (+bias per row) ----------------
// A row-major [M,K], B row-major [K,N], C row-major [M,N]. All dims divisible by tiles.
template <int BM, int BN, int BK, int TM, int TN>
__global__ void sgemm_bias(const float* __restrict__ Aall, long long sA,
                           const float* __restrict__ Ball, long long sB,
                           float* __restrict__ Call, long long sC,
                           const float* __restrict__ biasAll, long long sBias,
                           int M, int N, int K) {
    constexpr int THREADS = (BM / TM) * (BN / TN);
    const int b = blockIdx.z;
    const float* A = Aall + (long long)b * sA;
    const float* B = Ball + (long long)b * sB;
    float* C = Call + (long long)b * sC;

    __shared__ float As[BK][BM];
    __shared__ float Bs[BK][BN];

    const int tid  = threadIdx.x;
    const int tcol = tid % (BN / TN);
    const int trow = tid / (BN / TN);

    const float* Ag = A + (long long)blockIdx.y * BM * K;
    const float* Bg = B + blockIdx.x * BN;

    float acc[TM][TN];
#pragma unroll
    for (int i = 0; i < TM; ++i)
#pragma unroll
        for (int j = 0; j < TN; ++j) acc[i][j] = 0.f;

    for (int k0 = 0; k0 < K; k0 += BK) {
        // load A tile (BM x BK) transposed into As
#pragma unroll
        for (int it = 0; it < (BM * BK) / (THREADS * 4); ++it) {
            int idx = (tid + it * THREADS) * 4;
            int r = idx / BK, c = idx % BK;
            float4 v = *(const float4*)(Ag + (long long)r * K + k0 + c);
            As[c + 0][r] = v.x; As[c + 1][r] = v.y;
            As[c + 2][r] = v.z; As[c + 3][r] = v.w;
        }
        // load B tile (BK x BN)
#pragma unroll
        for (int it = 0; it < (BK * BN) / (THREADS * 4); ++it) {
            int idx = (tid + it * THREADS) * 4;
            int r = idx / BN, c = idx % BN;
            *(float4*)(&Bs[r][c]) = *(const float4*)(Bg + (long long)(k0 + r) * N + c);
        }
        __syncthreads();

        float ar[TM], br[TN];
#pragma unroll
        for (int k = 0; k < BK; ++k) {
#pragma unroll
            for (int i = 0; i < TM; ++i) ar[i] = As[k][trow * TM + i];
#pragma unroll
            for (int j = 0; j < TN; ++j) br[j] = Bs[k][tcol * TN + j];
#pragma unroll
            for (int i = 0; i < TM; ++i)
#pragma unroll
                for (int j = 0; j < TN; ++j) acc[i][j] = fmaf(ar[i], br[j], acc[i][j]);
        }
        __syncthreads();
    }

#pragma unroll
    for (int i = 0; i < TM; ++i) {
        int row = blockIdx.y * BM + trow * TM + i;
        float bias = biasAll ? biasAll[(long long)b * sBias + row] : 0.f;
        float* crow = C + (long long)row * N + blockIdx.x * BN + tcol * TN;
#pragma unroll
        for (int j = 0; j < TN; j += 4) {
            float4 v;
            v.x = acc[i][j + 0] + bias;
            v.y = acc[i][j + 1] + bias;
            v.z = acc[i][j + 2] + bias;
            v.w = acc[i][j + 3] + bias;
            *(float4*)(crow + j) = v;
        }
    }
}

// ---------------- K4b: bias_p[n,c] = w_out[c,:] . tb[n,:] + b_out[c] ----------------
__global__ void biasp_kernel(const float* __restrict__ w_out,
                             const float* __restrict__ b_out) {
    const int n = blockIdx.x;
    const int c = threadIdx.x; // 256
    __shared__ float tbs[DI];
    if (c < DI) tbs[c] = d_tb[n * DI + c];
    __syncthreads();
    float d = 0.f;
    const float* wr = w_out + (size_t)c * DI;
#pragma unroll 4
    for (int j = 0; j < DI; ++j) d = fmaf(wr[j], tbs[j], d);
    d_biasp[n * DIM + c] = d + b_out[c];
}

// ---------------- K6: per-channel sum & sumsq of p ----------------
// grid = NB*DIM blocks (same layout as p), atomics into d_chsum/d_chsumsq
__global__ void stats_kernel() {
    const float4* src = (const float4*)d_p + (size_t)blockIdx.x * 1024;
    float s = 0.f, s2 = 0.f;
#pragma unroll
    for (int it = 0; it < 4; ++it) {
        float4 v = src[it * 256 + threadIdx.x];
        s  += v.x + v.y + v.z + v.w;
        s2 += v.x * v.x + v.y * v.y + v.z * v.z + v.w * v.w;
    }
#pragma unroll
    for (int o = 16; o; o >>= 1) {
        s  += __shfl_down_sync(0xffffffffu, s, o);
        s2 += __shfl_down_sync(0xffffffffu, s2, o);
    }
    __shared__ float ws[8], ws2[8];
    if ((threadIdx.x & 31) == 0) { ws[threadIdx.x >> 5] = s; ws2[threadIdx.x >> 5] = s2; }
    __syncthreads();
    if (threadIdx.x < 8) {
        s = ws[threadIdx.x]; s2 = ws2[threadIdx.x];
#pragma unroll
        for (int o = 4; o; o >>= 1) {
            s  += __shfl_down_sync(0xffu, s, o);
            s2 += __shfl_down_sync(0xffu, s2, o);
        }
        if (threadIdx.x == 0) {
            int c = blockIdx.x & 255;
            atomicAdd(&d_chsum[c], s);
            atomicAdd(&d_chsumsq[c], s2);
        }
    }
}

// ---------------- K7: finalize BN scale/shift ----------------
__global__ void finalize_kernel(const float* __restrict__ gamma,
                                const float* __restrict__ beta) {
    int c = threadIdx.x; // 256
    const float inv_cnt = 1.f / (float)CNT;
    float mean = d_chsum[c] * inv_cnt;
    float var  = d_chsumsq[c] * inv_cnt - mean * mean;
    float a = gamma[c] * rsqrtf(var + 1e-5f);
    d_scale[c] = a;
    d_shift[c] = beta[c] - a * mean;
}

// ---------------- K8: out = x + scale[c]*p + shift[c] ----------------
__global__ void out_kernel(const float* __restrict__ x, float* __restrict__ out) {
    size_t gid = (size_t)blockIdx.x * 256 + threadIdx.x; // float4 index
    int c = (int)((gid >> 10) & 255);                    // (gid*4 / 4096) % 256
    float a = d_scale[c], b = d_shift[c];
    float4 xv = ((const float4*)x)[gid];
    float4 pv = ((const float4*)d_p)[gid];
    float4 o;
    o.x = fmaf(a, pv.x, xv.x + b);
    o.y = fmaf(a, pv.y, xv.y + b);
    o.z = fmaf(a, pv.z, xv.z + b);
    o.w = fmaf(a, pv.w, xv.w + b);
    ((float4*)out)[gid] = o;
}

// ---------------- launch ----------------
extern "C" void kernel_launch(void* const* d_in, const int* in_sizes, int n_in,
                              void* d_out, int out_size) {
    const float* x       = (const float*)d_in[0];
    const float* w_theta = (const float*)d_in[1];
    const float* b_theta = (const float*)d_in[2];
    const float* w_phi   = (const float*)d_in[3];
    const float* b_phi   = (const float*)d_in[4];
    const float* w_g     = (const float*)d_in[5];
    const float* b_g     = (const float*)d_in[6];
    const float* w_out   = (const float*)d_in[7];
    const float* b_out   = (const float*)d_in[8];
    const float* gamma   = (const float*)d_in[9];
    const float* beta    = (const float*)d_in[10];
    float* out = (float*)d_out;
    (void)in_sizes; (void)n_in; (void)out_size;

    float *p_tp, *p_T, *p_W2, *p_p, *p_biasp;
    cudaGetSymbolAddress((void**)&p_tp,    d_tp);
    cudaGetSymbolAddress((void**)&p_T,     d_T);
    cudaGetSymbolAddress((void**)&p_W2,    d_W2);
    cudaGetSymbolAddress((void**)&p_p,     d_p);
    cudaGetSymbolAddress((void**)&p_biasp, d_biasp);

    zero_stats_kernel<<<1, 256>>>();
    xsum_kernel<<<NB * DIM, 256>>>(x);
    attn_kernel<<<NB, 128>>>(w_theta, b_theta, w_phi, b_phi, b_g);

    // T[n] = theta_phi[n] @ w_g : [128,256], K=128
    sgemm_bias<128, 128, 16, 8, 8><<<dim3(2, 1, NB), 256>>>(
        p_tp, (long long)DI * DI, w_g, 0, p_T, (long long)DI * DIM,
        nullptr, 0, DI, DIM, DI);

    // W2[n] = w_out @ T[n] : [256,256], K=128
    sgemm_bias<128, 128, 16, 8, 8><<<dim3(2, 2, NB), 256>>>(
        w_out, 0, p_T, (long long)DI * DIM, p_W2, (long long)DIM * DIM,
        nullptr, 0, DIM, DIM, DI);

    biasp_kernel<<<NB, 256>>>(w_out, b_out);

    // p[n] = W2[n] @ x[n] + bias_p[n] : [256,4096], K=256
    sgemm_bias<128, 128, 16, 8, 8><<<dim3(HW / 128, 2, NB), 256>>>(
        p_W2, (long long)DIM * DIM, x, (long long)DIM * HW, p_p, (long long)DIM * HW,
        p_biasp, DIM, DIM, HW, DIM);

    stats_kernel<<<NB * DIM, 256>>>();
    finalize_kernel<<<1, 256>>>(gamma, beta);
    out_kernel<<<(size_t)NB * DIM * HW / 4 / 256, 256>>>(x, out);
}

// round 4
// speedup vs baseline: 1.2637x; 1.2637x over previous
#include <cuda_runtime.h>
#include <cuda_bf16.h>
#include <math.h>
#include <stdint.h>

#define NB   32
#define DIM  256
#define DI   128
#define HW   4096
#define CNT  (NB*HW)

// ---------------------------------------------------------------------------
// Device scratch (no allocations allowed anywhere)
// ---------------------------------------------------------------------------
__device__ float  d_xsum[NB*DIM];
__device__ float  d_tp[NB*DI*DI];
__device__ float  d_tb[NB*DI];
__device__ float  d_T[NB*DI*DIM];
__device__ float  d_W2[NB*DIM*DIM];
__device__ float  d_biasp[NB*DIM];
__device__ __nv_bfloat16 d_W2h[(size_t)NB*DIM*DIM];
__device__ __nv_bfloat16 d_W2l[(size_t)NB*DIM*DIM];
__device__ float  d_p[(size_t)NB*DIM*HW];   // pre-BN output (134 MB)
__device__ float  d_chsum[DIM];
__device__ float  d_chsumsq[DIM];
__device__ float  d_scale[DIM];
__device__ float  d_shift[DIM];

// ---------------------------------------------------------------------------
// K0: zero BN accumulators
// ---------------------------------------------------------------------------
__global__ void zero_stats_kernel() {
    int t = threadIdx.x;
    d_chsum[t] = 0.f;
    d_chsumsq[t] = 0.f;
}

// ---------------------------------------------------------------------------
// K1: per-(n,c) channel sums of x  (proven in R1)
// ---------------------------------------------------------------------------
__global__ void xsum_kernel(const float* __restrict__ x) {
    const float4* src = (const float4*)x + (size_t)blockIdx.x * 1024;
    float s = 0.f;
#pragma unroll
    for (int it = 0; it < 4; ++it) {
        float4 v = src[it * 256 + threadIdx.x];
        s += v.x + v.y + v.z + v.w;
    }
#pragma unroll
    for (int o = 16; o; o >>= 1) s += __shfl_down_sync(0xffffffffu, s, o);
    __shared__ float ws[8];
    if ((threadIdx.x & 31) == 0) ws[threadIdx.x >> 5] = s;
    __syncthreads();
    if (threadIdx.x < 8) {
        s = ws[threadIdx.x];
#pragma unroll
        for (int o = 4; o; o >>= 1) s += __shfl_down_sync(0xffu, s, o);
        if (threadIdx.x == 0) d_xsum[blockIdx.x] = s;
    }
}

// ---------------------------------------------------------------------------
// K2: attention prep  (proven in R1)
// ---------------------------------------------------------------------------
__global__ void attn_kernel(const float* __restrict__ w_theta,
                            const float* __restrict__ b_theta,
                            const float* __restrict__ w_phi,
                            const float* __restrict__ b_phi,
                            const float* __restrict__ b_g) {
    const int n = blockIdx.x;
    const int i = threadIdx.x;
    __shared__ float xs[DIM];
    __shared__ float ts[DI];
    __shared__ float ps[DI];
    xs[i]       = d_xsum[n * DIM + i];
    xs[i + 128] = d_xsum[n * DIM + 128 + i];
    __syncthreads();

    float dt = 0.f, dp = 0.f;
    const float* wt = w_theta + (size_t)i * DIM;
    const float* wp = w_phi   + (size_t)i * DIM;
#pragma unroll 4
    for (int k = 0; k < DIM; ++k) {
        float xv = xs[k];
        dt = fmaf(wt[k], xv, dt);
        dp = fmaf(wp[k], xv, dp);
    }
    ts[i] = dt * (1.f / 16.f) + 256.f * b_theta[i];
    ps[i] = dp * (1.f / 16.f) + 256.f * b_phi[i];
    __syncthreads();

    const float sc = 0.08838834764831845f;
    float a = ts[i] * sc;
    float m = -1e30f;
#pragma unroll 4
    for (int j = 0; j < DI; ++j) m = fmaxf(m, a * ps[j]);
    float sum = 0.f;
#pragma unroll 4
    for (int j = 0; j < DI; ++j) sum += expf(a * ps[j] - m);
    float inv = 1.f / sum;

    float tbacc = 0.f;
    float* row = d_tp + ((size_t)n * DI + i) * DI;
#pragma unroll 4
    for (int j = 0; j < DI; ++j) {
        float e = expf(a * ps[j] - m) * inv;
        row[j] = e;
        tbacc = fmaf(e, b_g[j], tbacc);
    }
    d_tb[n * DI + i] = tbacc;
}

// ---------------------------------------------------------------------------
// small SIMT batched SGEMM for T and W2 (tiny, proven in R1)
// ---------------------------------------------------------------------------
template <int BM, int BN, int BK, int TM, int TN>
__global__ void sgemm_bias(const float* __restrict__ Aall, long long sA,
                           const float* __restrict__ Ball, long long sB,
                           float* __restrict__ Call, long long sC,
                           const float* __restrict__ biasAll, long long sBias,
                           int M, int N, int K) {
    constexpr int THREADS = (BM / TM) * (BN / TN);
    const int b = blockIdx.z;
    const float* A = Aall + (long long)b * sA;
    const float* B = Ball + (long long)b * sB;
    float* C = Call + (long long)b * sC;

    __shared__ float As[BK][BM];
    __shared__ float Bs[BK][BN];

    const int tid  = threadIdx.x;
    const int tcol = tid % (BN / TN);
    const int trow = tid / (BN / TN);

    const float* Ag = A + (long long)blockIdx.y * BM * K;
    const float* Bg = B + blockIdx.x * BN;

    float acc[TM][TN];
#pragma unroll
    for (int i = 0; i < TM; ++i)
#pragma unroll
        for (int j = 0; j < TN; ++j) acc[i][j] = 0.f;

    for (int k0 = 0; k0 < K; k0 += BK) {
#pragma unroll
        for (int it = 0; it < (BM * BK) / (THREADS * 4); ++it) {
            int idx = (tid + it * THREADS) * 4;
            int r = idx / BK, c = idx % BK;
            float4 v = *(const float4*)(Ag + (long long)r * K + k0 + c);
            As[c + 0][r] = v.x; As[c + 1][r] = v.y;
            As[c + 2][r] = v.z; As[c + 3][r] = v.w;
        }
#pragma unroll
        for (int it = 0; it < (BK * BN) / (THREADS * 4); ++it) {
            int idx = (tid + it * THREADS) * 4;
            int r = idx / BN, c = idx % BN;
            *(float4*)(&Bs[r][c]) = *(const float4*)(Bg + (long long)(k0 + r) * N + c);
        }
        __syncthreads();

        float ar[TM], br[TN];
#pragma unroll
        for (int k = 0; k < BK; ++k) {
#pragma unroll
            for (int i = 0; i < TM; ++i) ar[i] = As[k][trow * TM + i];
#pragma unroll
            for (int j = 0; j < TN; ++j) br[j] = Bs[k][tcol * TN + j];
#pragma unroll
            for (int i = 0; i < TM; ++i)
#pragma unroll
                for (int j = 0; j < TN; ++j) acc[i][j] = fmaf(ar[i], br[j], acc[i][j]);
        }
        __syncthreads();
    }

#pragma unroll
    for (int i = 0; i < TM; ++i) {
        int row = blockIdx.y * BM + trow * TM + i;
        float bias = biasAll ? biasAll[(long long)b * sBias + row] : 0.f;
        float* crow = C + (long long)row * N + blockIdx.x * BN + tcol * TN;
#pragma unroll
        for (int j = 0; j < TN; j += 4) {
            float4 v;
            v.x = acc[i][j + 0] + bias;
            v.y = acc[i][j + 1] + bias;
            v.z = acc[i][j + 2] + bias;
            v.w = acc[i][j + 3] + bias;
            *(float4*)(crow + j) = v;
        }
    }
}

// ---------------------------------------------------------------------------
// K4b: bias_p[n,c] = w_out[c,:] . tb[n,:] + b_out[c]   (proven in R1)
// ---------------------------------------------------------------------------
__global__ void biasp_kernel(const float* __restrict__ w_out,
                             const float* __restrict__ b_out) {
    const int n = blockIdx.x;
    const int c = threadIdx.x;
    __shared__ float tbs[DI];
    if (c < DI) tbs[c] = d_tb[n * DI + c];
    __syncthreads();
    float d = 0.f;
    const float* wr = w_out + (size_t)c * DI;
#pragma unroll 4
    for (int j = 0; j < DI; ++j) d = fmaf(wr[j], tbs[j], d);
    d_biasp[n * DIM + c] = d + b_out[c];
}

// ---------------------------------------------------------------------------
// K5: split W2 fp32 -> bf16 hi/lo (row-major [n][256][256])
// ---------------------------------------------------------------------------
__global__ void w2split_kernel() {
    const int n = blockIdx.x;
    const float* W = d_W2 + (size_t)n * 65536;
    __nv_bfloat16* Hh = d_W2h + (size_t)n * 65536;
    __nv_bfloat16* Hl = d_W2l + (size_t)n * 65536;
    for (int i = threadIdx.x; i < 65536; i += 256) {
        float v = W[i];
        __nv_bfloat16 h = __float2bfloat16(v);
        __nv_bfloat16 l = __float2bfloat16(v - __bfloat162float(h));
        Hh[i] = h;
        Hl[i] = l;
    }
}

// ---------------------------------------------------------------------------
// K6: main tensor-core GEMM (mma.sync bf16 split-3) + fused BN stats.
// Per CTA: C[128 rows(c_out), 128 cols(hw)] = W2_half @ x[n], K=256.
// 256 threads = 8 warps (2 m x 4 n), warp tile 64x32, frag m16n8k16.
// A (W2 hi/lo) fully resident in smem (padded stride 264 bf16).
// B (x) converted fp32->bf16 hi/lo per K-chunk of 64 into double-buffered smem
// layout [kpair][hw] u32-packed, padded stride 136 words.
// Epilogue: p = C + bias_p -> global; per-channel sum/sumsq -> atomics.
// ---------------------------------------------------------------------------
#define AK   264                       // A smem row stride (bf16 units)
#define SM_AH 0
#define SM_AL (128*AK*2)               // 67584
#define SM_B  (2*128*AK*2)             // 135168
#define BROW 136                       // B smem kpair-row stride (u32 words)
#define BBUF (32*BROW*4)               // 17408 bytes per component per buffer
#define GS   (SM_B + 4*BBUF)           // 204800 bytes total

__device__ __forceinline__ void mma16816(float* c, const uint32_t* a, const uint32_t* b) {
    asm volatile("mma.sync.aligned.m16n8k16.row.col.f32.bf16.bf16.f32 "
        "{%0,%1,%2,%3}, {%4,%5,%6,%7}, {%8,%9}, {%0,%1,%2,%3};"
        : "+f"(c[0]), "+f"(c[1]), "+f"(c[2]), "+f"(c[3])
        : "r"(a[0]), "r"(a[1]), "r"(a[2]), "r"(a[3]), "r"(b[0]), "r"(b[1]));
}

__global__ void __launch_bounds__(256, 1) mma_gemm(const float* __restrict__ x) {
    extern __shared__ char smem[];
    const int tid  = threadIdx.x;
    const int lane = tid & 31;
    const int wid  = tid >> 5;
    const int warp_m = wid >> 2;   // 0..1
    const int warp_n = wid & 3;    // 0..3
    const int bid = blockIdx.x;
    const int m = bid & 1, hwt = (bid >> 1) & 31, n = bid >> 6;

    // ---- load A (W2 hi/lo bf16) into padded smem ----
    {
        const uint4* gh = (const uint4*)(d_W2h + ((size_t)n * 256 + m * 128) * 256);
        const uint4* gl = (const uint4*)(d_W2l + ((size_t)n * 256 + m * 128) * 256);
#pragma unroll
        for (int i = 0; i < 16; ++i) {
            int idx = i * 256 + tid;          // 4096 uint4 = 128 rows x 32
            int r = idx >> 5, c = idx & 31;
            *(uint4*)(smem + SM_AH + r * (AK * 2) + c * 16) = gh[idx];
            *(uint4*)(smem + SM_AL + r * (AK * 2) + c * 16) = gl[idx];
        }
    }

    float acc[4][4][4];
#pragma unroll
    for (int a = 0; a < 4; ++a)
#pragma unroll
        for (int b = 0; b < 4; ++b)
#pragma unroll
            for (int r = 0; r < 4; ++r) acc[a][b][r] = 0.f;

    const float* xg = x + (size_t)n * 256 * 4096 + hwt * 128;

    // prefetch chunk 0: per thread 4 items, each = 2 rows x 4 hw floats
    float4 pre[8];
    {
#pragma unroll
        for (int it = 0; it < 4; ++it) {
            int item = it * 256 + tid;
            int kp = item >> 5, hw = (item & 31) * 4;
            pre[it * 2 + 0] = *(const float4*)(xg + (size_t)(2 * kp) * 4096 + hw);
            pre[it * 2 + 1] = *(const float4*)(xg + (size_t)(2 * kp + 1) * 4096 + hw);
        }
    }

    for (int c = 0; c < 4; ++c) {
        const int buf = c & 1;
        const uint32_t bh_base = SM_B + buf * 2 * BBUF;
        const uint32_t bl_base = bh_base + BBUF;

        // ---- convert prefetched fp32 -> bf16 hi/lo packed u32 [kpair][hw] ----
#pragma unroll
        for (int it = 0; it < 4; ++it) {
            int item = it * 256 + tid;
            int kp = item >> 5, hw = (item & 31) * 4;
            float4 v0 = pre[it * 2 + 0];
            float4 v1 = pre[it * 2 + 1];
            uint32_t wh[4], wl[4];
            const float* f0 = (const float*)&v0;
            const float* f1 = (const float*)&v1;
#pragma unroll
            for (int e = 0; e < 4; ++e) {
                __nv_bfloat16 h0 = __float2bfloat16(f0[e]);
                __nv_bfloat16 h1 = __float2bfloat16(f1[e]);
                __nv_bfloat16 l0 = __float2bfloat16(f0[e] - __bfloat162float(h0));
                __nv_bfloat16 l1 = __float2bfloat16(f1[e] - __bfloat162float(h1));
                wh[e] = (uint32_t)__bfloat16_as_ushort(h0) | ((uint32_t)__bfloat16_as_ushort(h1) << 16);
                wl[e] = (uint32_t)__bfloat16_as_ushort(l0) | ((uint32_t)__bfloat16_as_ushort(l1) << 16);
            }
            *(uint4*)(smem + bh_base + (kp * BROW + hw) * 4) = make_uint4(wh[0], wh[1], wh[2], wh[3]);
            *(uint4*)(smem + bl_base + (kp * BROW + hw) * 4) = make_uint4(wl[0], wl[1], wl[2], wl[3]);
        }
        __syncthreads();

        // ---- prefetch next chunk while computing this one ----
        if (c < 3) {
            const float* xg2 = xg + (size_t)((c + 1) * 64) * 4096;
#pragma unroll
            for (int it = 0; it < 4; ++it) {
                int item = it * 256 + tid;
                int kp = item >> 5, hw = (item & 31) * 4;
                pre[it * 2 + 0] = *(const float4*)(xg2 + (size_t)(2 * kp) * 4096 + hw);
                pre[it * 2 + 1] = *(const float4*)(xg2 + (size_t)(2 * kp + 1) * 4096 + hw);
            }
        }

        // ---- compute: 4 k16 steps (k0 is ABSOLUTE k into A smem: chunk offset!) ----
#pragma unroll
        for (int ks = 0; ks < 4; ++ks) {
            uint32_t ah[4][4], al[4][4];
            const int k0 = c * 64 + ks * 16 + (lane & 3) * 2;   // FIXED: + c*64
#pragma unroll
            for (int mf = 0; mf < 4; ++mf) {
                int r0 = warp_m * 64 + mf * 16 + (lane >> 2);
                ah[mf][0] = *(const uint32_t*)(smem + SM_AH + r0 * (AK * 2) + k0 * 2);
                ah[mf][1] = *(const uint32_t*)(smem + SM_AH + (r0 + 8) * (AK * 2) + k0 * 2);
                ah[mf][2] = *(const uint32_t*)(smem + SM_AH + r0 * (AK * 2) + (k0 + 8) * 2);
                ah[mf][3] = *(const uint32_t*)(smem + SM_AH + (r0 + 8) * (AK * 2) + (k0 + 8) * 2);
                al[mf][0] = *(const uint32_t*)(smem + SM_AL + r0 * (AK * 2) + k0 * 2);
                al[mf][1] = *(const uint32_t*)(smem + SM_AL + (r0 + 8) * (AK * 2) + k0 * 2);
                al[mf][2] = *(const uint32_t*)(smem + SM_AL + r0 * (AK * 2) + (k0 + 8) * 2);
                al[mf][3] = *(const uint32_t*)(smem + SM_AL + (r0 + 8) * (AK * 2) + (k0 + 8) * 2);
            }
            uint32_t bh[4][2], bl[4][2];
            const int kp0 = ks * 8 + (lane & 3);
#pragma unroll
            for (int nf = 0; nf < 4; ++nf) {
                int col = warp_n * 32 + nf * 8 + (lane >> 2);
                bh[nf][0] = *(const uint32_t*)(smem + bh_base + (kp0 * BROW + col) * 4);
                bh[nf][1] = *(const uint32_t*)(smem + bh_base + ((kp0 + 4) * BROW + col) * 4);
                bl[nf][0] = *(const uint32_t*)(smem + bl_base + (kp0 * BROW + col) * 4);
                bl[nf][1] = *(const uint32_t*)(smem + bl_base + ((kp0 + 4) * BROW + col) * 4);
            }
#pragma unroll
            for (int mf = 0; mf < 4; ++mf)
#pragma unroll
                for (int nf = 0; nf < 4; ++nf) {
                    mma16816(acc[mf][nf], ah[mf], bh[nf]);
                    mma16816(acc[mf][nf], ah[mf], bl[nf]);
                    mma16816(acc[mf][nf], al[mf], bh[nf]);
                }
        }
        __syncthreads();   // all reads of buf done before it is overwritten (c+2)
    }

    // ---- epilogue: p = acc + bias; fused per-channel stats ----
    float* racc = (float*)(smem + SM_B);   // 128 rows x {sum, sumsq}
    racc[tid] = 0.f;
    __syncthreads();

    const int colbase = warp_n * 32 + (lane & 3) * 2;
    float* pg = d_p + ((size_t)n * 256 + m * 128) * 4096 + hwt * 128;
    const float* biasg = d_biasp + n * 256 + m * 128;
#pragma unroll
    for (int mf = 0; mf < 4; ++mf) {
#pragma unroll
        for (int half = 0; half < 2; ++half) {
            int row = warp_m * 64 + mf * 16 + (lane >> 2) + half * 8;
            float bias = biasg[row];
            float s = 0.f, s2 = 0.f;
#pragma unroll
            for (int nf = 0; nf < 4; ++nf) {
                float v0 = acc[mf][nf][half * 2 + 0] + bias;
                float v1 = acc[mf][nf][half * 2 + 1] + bias;
                s += v0 + v1;
                s2 += v0 * v0 + v1 * v1;
                *(float2*)(pg + (size_t)row * 4096 + nf * 8 + colbase) = make_float2(v0, v1);
            }
            s  += __shfl_xor_sync(0xffffffffu, s, 1);
            s  += __shfl_xor_sync(0xffffffffu, s, 2);
            s2 += __shfl_xor_sync(0xffffffffu, s2, 1);
            s2 += __shfl_xor_sync(0xffffffffu, s2, 2);
            if ((lane & 3) == 0) {
                atomicAdd(&racc[row * 2],     s);
                atomicAdd(&racc[row * 2 + 1], s2);
            }
        }
    }
    __syncthreads();
    if (tid < 128) {
        atomicAdd(&d_chsum[m * 128 + tid],   racc[tid * 2]);
        atomicAdd(&d_chsumsq[m * 128 + tid], racc[tid * 2 + 1]);
    }
}

// ---------------------------------------------------------------------------
// K7: finalize BN scale/shift
// ---------------------------------------------------------------------------
__global__ void finalize_kernel(const float* __restrict__ gamma,
                                const float* __restrict__ beta) {
    int c = threadIdx.x;
    const float inv_cnt = 1.f / (float)CNT;
    float mean = d_chsum[c] * inv_cnt;
    float var  = d_chsumsq[c] * inv_cnt - mean * mean;
    float a = gamma[c] * rsqrtf(var + 1e-5f);
    d_scale[c] = a;
    d_shift[c] = beta[c] - a * mean;
}

// ---------------------------------------------------------------------------
// K8: out = x + scale[c]*p + shift[c]
// ---------------------------------------------------------------------------
__global__ void out_kernel(const float* __restrict__ x, float* __restrict__ out) {
    size_t gid = (size_t)blockIdx.x * 256 + threadIdx.x;
    int c = (int)((gid >> 10) & 255);
    float a = d_scale[c], b = d_shift[c];
    float4 xv = ((const float4*)x)[gid];
    float4 pv = ((const float4*)d_p)[gid];
    float4 o;
    o.x = fmaf(a, pv.x, xv.x + b);
    o.y = fmaf(a, pv.y, xv.y + b);
    o.z = fmaf(a, pv.z, xv.z + b);
    o.w = fmaf(a, pv.w, xv.w + b);
    ((float4*)out)[gid] = o;
}

// ---------------------------------------------------------------------------
// launch
// ---------------------------------------------------------------------------
extern "C" void kernel_launch(void* const* d_in, const int* in_sizes, int n_in,
                              void* d_out, int out_size) {
    const float* x       = (const float*)d_in[0];
    const float* w_theta = (const float*)d_in[1];
    const float* b_theta = (const float*)d_in[2];
    const float* w_phi   = (const float*)d_in[3];
    const float* b_phi   = (const float*)d_in[4];
    const float* w_g     = (const float*)d_in[5];
    const float* b_g     = (const float*)d_in[6];
    const float* w_out   = (const float*)d_in[7];
    const float* b_out   = (const float*)d_in[8];
    const float* gamma   = (const float*)d_in[9];
    const float* beta    = (const float*)d_in[10];
    float* out = (float*)d_out;
    (void)in_sizes; (void)n_in; (void)out_size;

    float *p_tp, *p_T, *p_W2;
    cudaGetSymbolAddress((void**)&p_tp, d_tp);
    cudaGetSymbolAddress((void**)&p_T,  d_T);
    cudaGetSymbolAddress((void**)&p_W2, d_W2);

    cudaFuncSetAttribute(mma_gemm, cudaFuncAttributeMaxDynamicSharedMemorySize, GS);

    zero_stats_kernel<<<1, 256>>>();
    xsum_kernel<<<NB * DIM, 256>>>(x);
    attn_kernel<<<NB, 128>>>(w_theta, b_theta, w_phi, b_phi, b_g);

    // T[n] = tp[n] @ w_g : [128,256], K=128
    sgemm_bias<128, 128, 16, 8, 8><<<dim3(2, 1, NB), 256>>>(
        p_tp, (long long)DI * DI, w_g, 0, p_T, (long long)DI * DIM,
        nullptr, 0, DI, DIM, DI);
    // W2[n] = w_out @ T[n] : [256,256], K=128
    sgemm_bias<128, 128, 16, 8, 8><<<dim3(2, 2, NB), 256>>>(
        w_out, 0, p_T, (long long)DI * DIM, p_W2, (long long)DIM * DIM,
        nullptr, 0, DIM, DIM, DI);

    biasp_kernel<<<NB, 256>>>(w_out, b_out);
    w2split_kernel<<<NB, 256>>>();

    mma_gemm<<<2048, 256, GS>>>(x);

    finalize_kernel<<<1, 256>>>(gamma, beta);
    out_kernel<<<(size_t)NB * DIM * HW / 4 / 256, 256>>>(x, out);
}

// round 5
// speedup vs baseline: 1.4670x; 1.1609x over previous
#include <cuda_runtime.h>
#include <cuda_bf16.h>
#include <cuda_fp16.h>
#include <math.h>
#include <stdint.h>

#define NB   32
#define DIM  256
#define DI   128
#define HW   4096
#define CNT  (NB*HW)
#define W2SCALE 256.0f   // scale W2 & bias_p; BN normalization cancels it exactly

// ---------------------------------------------------------------------------
// Device scratch (no allocations allowed anywhere)
// ---------------------------------------------------------------------------
__device__ float  d_xsum[NB*DIM];
__device__ float  d_tp[NB*DI*DI];
__device__ float  d_tb[NB*DI];
__device__ float  d_T[NB*DI*DIM];
__device__ float  d_W2[NB*DIM*DIM];
__device__ float  d_biasp[NB*DIM];
__device__ __half d_W2h[(size_t)NB*DIM*DIM];
__device__ __half d_W2l[(size_t)NB*DIM*DIM];
__device__ float  d_p[(size_t)NB*DIM*HW];   // pre-BN output, scaled x256 (134 MB)
__device__ float  d_chsum[DIM];
__device__ float  d_chsumsq[DIM];
__device__ float  d_scale[DIM];
__device__ float  d_shift[DIM];

// ---------------------------------------------------------------------------
// K0: zero BN accumulators
// ---------------------------------------------------------------------------
__global__ void zero_stats_kernel() {
    int t = threadIdx.x;
    d_chsum[t] = 0.f;
    d_chsumsq[t] = 0.f;
}

// ---------------------------------------------------------------------------
// K1: per-(n,c) channel sums of x
// ---------------------------------------------------------------------------
__global__ void xsum_kernel(const float* __restrict__ x) {
    const float4* src = (const float4*)x + (size_t)blockIdx.x * 1024;
    float s = 0.f;
#pragma unroll
    for (int it = 0; it < 4; ++it) {
        float4 v = src[it * 256 + threadIdx.x];
        s += v.x + v.y + v.z + v.w;
    }
#pragma unroll
    for (int o = 16; o; o >>= 1) s += __shfl_down_sync(0xffffffffu, s, o);
    __shared__ float ws[8];
    if ((threadIdx.x & 31) == 0) ws[threadIdx.x >> 5] = s;
    __syncthreads();
    if (threadIdx.x < 8) {
        s = ws[threadIdx.x];
#pragma unroll
        for (int o = 4; o; o >>= 1) s += __shfl_down_sync(0xffu, s, o);
        if (threadIdx.x == 0) d_xsum[blockIdx.x] = s;
    }
}

// ---------------------------------------------------------------------------
// K2: attention prep
// ---------------------------------------------------------------------------
__global__ void attn_kernel(const float* __restrict__ w_theta,
                            const float* __restrict__ b_theta,
                            const float* __restrict__ w_phi,
                            const float* __restrict__ b_phi,
                            const float* __restrict__ b_g) {
    const int n = blockIdx.x;
    const int i = threadIdx.x;
    __shared__ float xs[DIM];
    __shared__ float ts[DI];
    __shared__ float ps[DI];
    xs[i]       = d_xsum[n * DIM + i];
    xs[i + 128] = d_xsum[n * DIM + 128 + i];
    __syncthreads();

    float dt = 0.f, dp = 0.f;
    const float* wt = w_theta + (size_t)i * DIM;
    const float* wp = w_phi   + (size_t)i * DIM;
#pragma unroll 4
    for (int k = 0; k < DIM; ++k) {
        float xv = xs[k];
        dt = fmaf(wt[k], xv, dt);
        dp = fmaf(wp[k], xv, dp);
    }
    ts[i] = dt * (1.f / 16.f) + 256.f * b_theta[i];
    ps[i] = dp * (1.f / 16.f) + 256.f * b_phi[i];
    __syncthreads();

    const float sc = 0.08838834764831845f;
    float a = ts[i] * sc;
    float m = -1e30f;
#pragma unroll 4
    for (int j = 0; j < DI; ++j) m = fmaxf(m, a * ps[j]);
    float sum = 0.f;
#pragma unroll 4
    for (int j = 0; j < DI; ++j) sum += expf(a * ps[j] - m);
    float inv = 1.f / sum;

    float tbacc = 0.f;
    float* row = d_tp + ((size_t)n * DI + i) * DI;
#pragma unroll 4
    for (int j = 0; j < DI; ++j) {
        float e = expf(a * ps[j] - m) * inv;
        row[j] = e;
        tbacc = fmaf(e, b_g[j], tbacc);
    }
    d_tb[n * DI + i] = tbacc;
}

// ---------------------------------------------------------------------------
// small SIMT batched SGEMM for T and W2 (64x64 tiles for better parallelism)
// ---------------------------------------------------------------------------
template <int BM, int BN, int BK, int TM, int TN>
__global__ void sgemm_bias(const float* __restrict__ Aall, long long sA,
                           const float* __restrict__ Ball, long long sB,
                           float* __restrict__ Call, long long sC,
                           int M, int N, int K) {
    constexpr int THREADS = (BM / TM) * (BN / TN);
    const int b = blockIdx.z;
    const float* A = Aall + (long long)b * sA;
    const float* B = Ball + (long long)b * sB;
    float* C = Call + (long long)b * sC;

    __shared__ float As[BK][BM];
    __shared__ float Bs[BK][BN];

    const int tid  = threadIdx.x;
    const int tcol = tid % (BN / TN);
    const int trow = tid / (BN / TN);

    const float* Ag = A + (long long)blockIdx.y * BM * K;
    const float* Bg = B + blockIdx.x * BN;

    float acc[TM][TN];
#pragma unroll
    for (int i = 0; i < TM; ++i)
#pragma unroll
        for (int j = 0; j < TN; ++j) acc[i][j] = 0.f;

    for (int k0 = 0; k0 < K; k0 += BK) {
#pragma unroll
        for (int it = 0; it < (BM * BK) / (THREADS * 4); ++it) {
            int idx = (tid + it * THREADS) * 4;
            int r = idx / BK, c = idx % BK;
            float4 v = *(const float4*)(Ag + (long long)r * K + k0 + c);
            As[c + 0][r] = v.x; As[c + 1][r] = v.y;
            As[c + 2][r] = v.z; As[c + 3][r] = v.w;
        }
#pragma unroll
        for (int it = 0; it < (BK * BN) / (THREADS * 4); ++it) {
            int idx = (tid + it * THREADS) * 4;
            int r = idx / BN, c = idx % BN;
            *(float4*)(&Bs[r][c]) = *(const float4*)(Bg + (long long)(k0 + r) * N + c);
        }
        __syncthreads();

        float ar[TM], br[TN];
#pragma unroll
        for (int k = 0; k < BK; ++k) {
#pragma unroll
            for (int i = 0; i < TM; ++i) ar[i] = As[k][trow * TM + i];
#pragma unroll
            for (int j = 0; j < TN; ++j) br[j] = Bs[k][tcol * TN + j];
#pragma unroll
            for (int i = 0; i < TM; ++i)
#pragma unroll
                for (int j = 0; j < TN; ++j) acc[i][j] = fmaf(ar[i], br[j], acc[i][j]);
        }
        __syncthreads();
    }

#pragma unroll
    for (int i = 0; i < TM; ++i) {
        int row = blockIdx.y * BM + trow * TM + i;
        float* crow = C + (long long)row * N + blockIdx.x * BN + tcol * TN;
#pragma unroll
        for (int j = 0; j < TN; j += 4) {
            float4 v;
            v.x = acc[i][j + 0]; v.y = acc[i][j + 1];
            v.z = acc[i][j + 2]; v.w = acc[i][j + 3];
            *(float4*)(crow + j) = v;
        }
    }
}

// ---------------------------------------------------------------------------
// K4b: bias_p[n,c] = (w_out[c,:] . tb[n,:] + b_out[c]) * W2SCALE
// ---------------------------------------------------------------------------
__global__ void biasp_kernel(const float* __restrict__ w_out,
                             const float* __restrict__ b_out) {
    const int n = blockIdx.x;
    const int c = threadIdx.x;
    __shared__ float tbs[DI];
    if (c < DI) tbs[c] = d_tb[n * DI + c];
    __syncthreads();
    float d = 0.f;
    const float* wr = w_out + (size_t)c * DI;
#pragma unroll 4
    for (int j = 0; j < DI; ++j) d = fmaf(wr[j], tbs[j], d);
    d_biasp[n * DIM + c] = (d + b_out[c]) * W2SCALE;
}

// ---------------------------------------------------------------------------
// K5: split W2*256 fp32 -> fp16 hi/lo (row-major [n][256][256])
// ---------------------------------------------------------------------------
__global__ void w2split_kernel() {
    const int n = blockIdx.x;
    const float* W = d_W2 + (size_t)n * 65536;
    __half* Hh = d_W2h + (size_t)n * 65536;
    __half* Hl = d_W2l + (size_t)n * 65536;
    for (int i = threadIdx.x; i < 65536; i += 256) {
        float v = W[i] * W2SCALE;
        __half h = __float2half_rn(v);
        __half l = __float2half_rn(v - __half2float(h));
        Hh[i] = h;
        Hl[i] = l;
    }
}

// ---------------------------------------------------------------------------
// K6: main tensor-core GEMM (mma.sync fp16, 2-product A-split) + fused stats.
// C[128 c_out,128 hw] = (W2h+W2l)_half @ x_fp16, K=256; p scaled x256.
// 256 threads = 8 warps (2m x 4n), warp tile 64x32, frag m16n8k16.
// A hi/lo resident in smem (stride 264 fp16). B single fp16, double-buffered,
// layout [kpair][hw] u32-packed, stride 136 words.
// ---------------------------------------------------------------------------
#define AK    264
#define SM_AH 0
#define SM_AL (128*AK*2)               // 67584
#define SM_B  (2*128*AK*2)             // 135168
#define BROW  136
#define BBUF  (32*BROW*4)              // 17408 bytes per buffer
#define GS    (SM_B + 2*BBUF)          // 169984 bytes

__device__ __forceinline__ void mma16816h(float* c, const uint32_t* a, const uint32_t* b) {
    asm volatile("mma.sync.aligned.m16n8k16.row.col.f32.f16.f16.f32 "
        "{%0,%1,%2,%3}, {%4,%5,%6,%7}, {%8,%9}, {%0,%1,%2,%3};"
        : "+f"(c[0]), "+f"(c[1]), "+f"(c[2]), "+f"(c[3])
        : "r"(a[0]), "r"(a[1]), "r"(a[2]), "r"(a[3]), "r"(b[0]), "r"(b[1]));
}

__global__ void __launch_bounds__(256, 1) mma_gemm(const float* __restrict__ x) {
    extern __shared__ char smem[];
    const int tid  = threadIdx.x;
    const int lane = tid & 31;
    const int wid  = tid >> 5;
    const int warp_m = wid >> 2;
    const int warp_n = wid & 3;
    const int bid = blockIdx.x;
    const int m = bid & 1, hwt = (bid >> 1) & 31, n = bid >> 6;

    // ---- load A (W2 hi/lo fp16) into padded smem ----
    {
        const uint4* gh = (const uint4*)(d_W2h + ((size_t)n * 256 + m * 128) * 256);
        const uint4* gl = (const uint4*)(d_W2l + ((size_t)n * 256 + m * 128) * 256);
#pragma unroll
        for (int i = 0; i < 16; ++i) {
            int idx = i * 256 + tid;
            int r = idx >> 5, c = idx & 31;
            *(uint4*)(smem + SM_AH + r * (AK * 2) + c * 16) = gh[idx];
            *(uint4*)(smem + SM_AL + r * (AK * 2) + c * 16) = gl[idx];
        }
    }

    float acc[4][4][4];
#pragma unroll
    for (int a = 0; a < 4; ++a)
#pragma unroll
        for (int b = 0; b < 4; ++b)
#pragma unroll
            for (int r = 0; r < 4; ++r) acc[a][b][r] = 0.f;

    const float* xg = x + (size_t)n * 256 * 4096 + hwt * 128;

    float4 pre[8];
#pragma unroll
    for (int it = 0; it < 4; ++it) {
        int item = it * 256 + tid;
        int kp = item >> 5, hw = (item & 31) * 4;
        pre[it * 2 + 0] = *(const float4*)(xg + (size_t)(2 * kp) * 4096 + hw);
        pre[it * 2 + 1] = *(const float4*)(xg + (size_t)(2 * kp + 1) * 4096 + hw);
    }

    for (int c = 0; c < 4; ++c) {
        const int buf = c & 1;
        const uint32_t b_base = SM_B + buf * BBUF;

        // ---- convert prefetched fp32 -> fp16 packed u32 [kpair][hw] ----
#pragma unroll
        for (int it = 0; it < 4; ++it) {
            int item = it * 256 + tid;
            int kp = item >> 5, hw = (item & 31) * 4;
            float4 v0 = pre[it * 2 + 0];
            float4 v1 = pre[it * 2 + 1];
            uint32_t w[4];
            const float* f0 = (const float*)&v0;
            const float* f1 = (const float*)&v1;
#pragma unroll
            for (int e = 0; e < 4; ++e) {
                __half h0 = __float2half_rn(f0[e]);
                __half h1 = __float2half_rn(f1[e]);
                w[e] = (uint32_t)__half_as_ushort(h0) | ((uint32_t)__half_as_ushort(h1) << 16);
            }
            *(uint4*)(smem + b_base + (kp * BROW + hw) * 4) = make_uint4(w[0], w[1], w[2], w[3]);
        }
        __syncthreads();

        // ---- prefetch next chunk while computing this one ----
        if (c < 3) {
            const float* xg2 = xg + (size_t)((c + 1) * 64) * 4096;
#pragma unroll
            for (int it = 0; it < 4; ++it) {
                int item = it * 256 + tid;
                int kp = item >> 5, hw = (item & 31) * 4;
                pre[it * 2 + 0] = *(const float4*)(xg2 + (size_t)(2 * kp) * 4096 + hw);
                pre[it * 2 + 1] = *(const float4*)(xg2 + (size_t)(2 * kp + 1) * 4096 + hw);
            }
        }

        // ---- compute: 4 k16 steps (absolute k into A smem) ----
#pragma unroll
        for (int ks = 0; ks < 4; ++ks) {
            uint32_t ah[4][4], al[4][4];
            const int k0 = c * 64 + ks * 16 + (lane & 3) * 2;
#pragma unroll
            for (int mf = 0; mf < 4; ++mf) {
                int r0 = warp_m * 64 + mf * 16 + (lane >> 2);
                ah[mf][0] = *(const uint32_t*)(smem + SM_AH + r0 * (AK * 2) + k0 * 2);
                ah[mf][1] = *(const uint32_t*)(smem + SM_AH + (r0 + 8) * (AK * 2) + k0 * 2);
                ah[mf][2] = *(const uint32_t*)(smem + SM_AH + r0 * (AK * 2) + (k0 + 8) * 2);
                ah[mf][3] = *(const uint32_t*)(smem + SM_AH + (r0 + 8) * (AK * 2) + (k0 + 8) * 2);
                al[mf][0] = *(const uint32_t*)(smem + SM_AL + r0 * (AK * 2) + k0 * 2);
                al[mf][1] = *(const uint32_t*)(smem + SM_AL + (r0 + 8) * (AK * 2) + k0 * 2);
                al[mf][2] = *(const uint32_t*)(smem + SM_AL + r0 * (AK * 2) + (k0 + 8) * 2);
                al[mf][3] = *(const uint32_t*)(smem + SM_AL + (r0 + 8) * (AK * 2) + (k0 + 8) * 2);
            }
            uint32_t bb[4][2];
            const int kp0 = ks * 8 + (lane & 3);
#pragma unroll
            for (int nf = 0; nf < 4; ++nf) {
                int col = warp_n * 32 + nf * 8 + (lane >> 2);
                bb[nf][0] = *(const uint32_t*)(smem + b_base + (kp0 * BROW + col) * 4);
                bb[nf][1] = *(const uint32_t*)(smem + b_base + ((kp0 + 4) * BROW + col) * 4);
            }
#pragma unroll
            for (int mf = 0; mf < 4; ++mf)
#pragma unroll
                for (int nf = 0; nf < 4; ++nf) {
                    mma16816h(acc[mf][nf], ah[mf], bb[nf]);
                    mma16816h(acc[mf][nf], al[mf], bb[nf]);
                }
        }
        __syncthreads();
    }

    // ---- epilogue: p = acc + bias; fused per-channel stats ----
    float* racc = (float*)(smem + SM_B);
    racc[tid] = 0.f;
    __syncthreads();

    const int colbase = warp_n * 32 + (lane & 3) * 2;
    float* pg = d_p + ((size_t)n * 256 + m * 128) * 4096 + hwt * 128;
    const float* biasg = d_biasp + n * 256 + m * 128;
#pragma unroll
    for (int mf = 0; mf < 4; ++mf) {
#pragma unroll
        for (int half = 0; half < 2; ++half) {
            int row = warp_m * 64 + mf * 16 + (lane >> 2) + half * 8;
            float bias = biasg[row];
            float s = 0.f, s2 = 0.f;
#pragma unroll
            for (int nf = 0; nf < 4; ++nf) {
                float v0 = acc[mf][nf][half * 2 + 0] + bias;
                float v1 = acc[mf][nf][half * 2 + 1] + bias;
                s += v0 + v1;
                s2 += v0 * v0 + v1 * v1;
                *(float2*)(pg + (size_t)row * 4096 + nf * 8 + colbase) = make_float2(v0, v1);
            }
            s  += __shfl_xor_sync(0xffffffffu, s, 1);
            s  += __shfl_xor_sync(0xffffffffu, s, 2);
            s2 += __shfl_xor_sync(0xffffffffu, s2, 1);
            s2 += __shfl_xor_sync(0xffffffffu, s2, 2);
            if ((lane & 3) == 0) {
                atomicAdd(&racc[row * 2],     s);
                atomicAdd(&racc[row * 2 + 1], s2);
            }
        }
    }
    __syncthreads();
    if (tid < 128) {
        atomicAdd(&d_chsum[m * 128 + tid],   racc[tid * 2]);
        atomicAdd(&d_chsumsq[m * 128 + tid], racc[tid * 2 + 1]);
    }
}

// ---------------------------------------------------------------------------
// K7: finalize BN scale/shift (operates on scaled p; self-consistent)
// ---------------------------------------------------------------------------
__global__ void finalize_kernel(const float* __restrict__ gamma,
                                const float* __restrict__ beta) {
    int c = threadIdx.x;
    const float inv_cnt = 1.f / (float)CNT;
    float mean = d_chsum[c] * inv_cnt;
    float var  = d_chsumsq[c] * inv_cnt - mean * mean;
    // p is scaled by W2SCALE: scale eps accordingly so result matches unscaled BN
    float a = gamma[c] * rsqrtf(var + 1e-5f * W2SCALE * W2SCALE);
    d_scale[c] = a;
    d_shift[c] = beta[c] - a * mean;
}

// ---------------------------------------------------------------------------
// K8: out = x + scale[c]*p + shift[c]
// ---------------------------------------------------------------------------
__global__ void out_kernel(const float* __restrict__ x, float* __restrict__ out) {
    size_t gid = (size_t)blockIdx.x * 256 + threadIdx.x;
    int c = (int)((gid >> 10) & 255);
    float a = d_scale[c], b = d_shift[c];
    float4 xv = ((const float4*)x)[gid];
    float4 pv = ((const float4*)d_p)[gid];
    float4 o;
    o.x = fmaf(a, pv.x, xv.x + b);
    o.y = fmaf(a, pv.y, xv.y + b);
    o.z = fmaf(a, pv.z, xv.z + b);
    o.w = fmaf(a, pv.w, xv.w + b);
    ((float4*)out)[gid] = o;
}

// ---------------------------------------------------------------------------
// launch
// ---------------------------------------------------------------------------
extern "C" void kernel_launch(void* const* d_in, const int* in_sizes, int n_in,
                              void* d_out, int out_size) {
    const float* x       = (const float*)d_in[0];
    const float* w_theta = (const float*)d_in[1];
    const float* b_theta = (const float*)d_in[2];
    const float* w_phi   = (const float*)d_in[3];
    const float* b_phi   = (const float*)d_in[4];
    const float* w_g     = (const float*)d_in[5];
    const float* b_g     = (const float*)d_in[6];
    const float* w_out   = (const float*)d_in[7];
    const float* b_out   = (const float*)d_in[8];
    const float* gamma   = (const float*)d_in[9];
    const float* beta    = (const float*)d_in[10];
    float* out = (float*)d_out;
    (void)in_sizes; (void)n_in; (void)out_size;

    float *p_tp, *p_T, *p_W2;
    cudaGetSymbolAddress((void**)&p_tp, d_tp);
    cudaGetSymbolAddress((void**)&p_T,  d_T);
    cudaGetSymbolAddress((void**)&p_W2, d_W2);

    cudaFuncSetAttribute(mma_gemm, cudaFuncAttributeMaxDynamicSharedMemorySize, GS);

    zero_stats_kernel<<<1, 256>>>();
    xsum_kernel<<<NB * DIM, 256>>>(x);
    attn_kernel<<<NB, 128>>>(w_theta, b_theta, w_phi, b_phi, b_g);

    // T[n] = tp[n] @ w_g : [128,256], K=128  (64x64 tiles -> 256 blocks)
    sgemm_bias<64, 64, 16, 4, 4><<<dim3(4, 2, NB), 256>>>(
        p_tp, (long long)DI * DI, w_g, 0, p_T, (long long)DI * DIM, DI, DIM, DI);
    // W2[n] = w_out @ T[n] : [256,256], K=128  (512 blocks)
    sgemm_bias<64, 64, 16, 4, 4><<<dim3(4, 4, NB), 256>>>(
        w_out, 0, p_T, (long long)DI * DIM, p_W2, (long long)DIM * DIM, DIM, DIM, DI);

    biasp_kernel<<<NB, 256>>>(w_out, b_out);
    w2split_kernel<<<NB, 256>>>();

    mma_gemm<<<2048, 256, GS>>>(x);

    finalize_kernel<<<1, 256>>>(gamma, beta);
    out_kernel<<<(size_t)NB * DIM * HW / 4 / 256, 256>>>(x, out);
}

// round 6
// speedup vs baseline: 1.4731x; 1.0041x over previous
#include <cuda_runtime.h>
#include <cuda_bf16.h>
#include <cuda_fp16.h>
#include <math.h>
#include <stdint.h>

#define NB   32
#define DIM  256
#define DI   128
#define HW   4096
#define CNT  (NB*HW)
#define W2SCALE 256.0f   // scale W2 & bias_p; BN normalization cancels it exactly

// ---------------------------------------------------------------------------
// Device scratch
// ---------------------------------------------------------------------------
__device__ float  d_xsum[NB*DIM];
__device__ float  d_tp[NB*DI*DI];
__device__ float  d_tb[NB*DI];
__device__ float  d_T[NB*DI*DIM];
__device__ float  d_W2[NB*DIM*DIM];
__device__ float  d_biasp[NB*DIM];
__device__ __half d_W2h[(size_t)NB*DIM*DIM];
__device__ __half d_W2l[(size_t)NB*DIM*DIM];
// x in fp16, k-pair packed: [n][hwt(32)][kp(128)][hw(128)] u32 = (k=2kp lo, 2kp+1 hi)
__device__ uint32_t d_xh[(size_t)NB*32*128*128];   // 67 MB
__device__ __half d_ph[(size_t)NB*DIM*HW];          // pre-BN p (scaled x256), 67 MB
__device__ float  d_chsum[DIM];
__device__ float  d_chsumsq[DIM];
__device__ float  d_scale[DIM];
__device__ float  d_shift[DIM];

__device__ __forceinline__ uint32_t smem_u32(const void* p) {
    uint32_t a;
    asm("{ .reg .u64 t; cvta.to.shared.u64 t, %1; cvt.u32.u64 %0, t; }" : "=r"(a) : "l"(p));
    return a;
}

// ---------------------------------------------------------------------------
// K0: zero BN accumulators
// ---------------------------------------------------------------------------
__global__ void zero_stats_kernel() {
    int t = threadIdx.x;
    d_chsum[t] = 0.f;
    d_chsumsq[t] = 0.f;
}

// ---------------------------------------------------------------------------
// K1: convert x -> packed fp16 blob + per-(n,c) channel sums (no atomics).
// grid (kp=128, n=32), 256 threads. Block owns rows k=2kp,2kp+1 of x[n].
// ---------------------------------------------------------------------------
__global__ void cvtxsum_kernel(const float* __restrict__ x) {
    const int kp = blockIdx.x, n = blockIdx.y, tid = threadIdx.x;
    const float4* r0 = (const float4*)(x + ((size_t)(n * 256 + 2 * kp)) * 4096);
    const float4* r1 = r0 + 1024;
    uint4* dst = (uint4*)d_xh;
    float s0 = 0.f, s1 = 0.f;
#pragma unroll
    for (int it = 0; it < 4; ++it) {
        int f4 = it * 256 + tid;                 // float4 index within the 4096-row
        float4 a = r0[f4];
        float4 b = r1[f4];
        s0 += a.x + a.y + a.z + a.w;
        s1 += b.x + b.y + b.z + b.w;
        __half2 h0 = __floats2half2_rn(a.x, b.x);
        __half2 h1 = __floats2half2_rn(a.y, b.y);
        __half2 h2 = __floats2half2_rn(a.z, b.z);
        __half2 h3 = __floats2half2_rn(a.w, b.w);
        uint4 w;
        w.x = *(uint32_t*)&h0; w.y = *(uint32_t*)&h1;
        w.z = *(uint32_t*)&h2; w.w = *(uint32_t*)&h3;
        int hwt = f4 >> 5;
        dst[(((size_t)(n * 32 + hwt) * 128 + kp) * 32) + (f4 & 31)] = w;
    }
    // block-reduce the two sums
#pragma unroll
    for (int o = 16; o; o >>= 1) {
        s0 += __shfl_down_sync(0xffffffffu, s0, o);
        s1 += __shfl_down_sync(0xffffffffu, s1, o);
    }
    __shared__ float w0[8], w1[8];
    if ((tid & 31) == 0) { w0[tid >> 5] = s0; w1[tid >> 5] = s1; }
    __syncthreads();
    if (tid < 8) {
        s0 = w0[tid]; s1 = w1[tid];
#pragma unroll
        for (int o = 4; o; o >>= 1) {
            s0 += __shfl_down_sync(0xffu, s0, o);
            s1 += __shfl_down_sync(0xffu, s1, o);
        }
        if (tid == 0) {
            d_xsum[n * 256 + 2 * kp]     = s0;
            d_xsum[n * 256 + 2 * kp + 1] = s1;
        }
    }
}

// ---------------------------------------------------------------------------
// K2: attention prep
// ---------------------------------------------------------------------------
__global__ void attn_kernel(const float* __restrict__ w_theta,
                            const float* __restrict__ b_theta,
                            const float* __restrict__ w_phi,
                            const float* __restrict__ b_phi,
                            const float* __restrict__ b_g) {
    const int n = blockIdx.x;
    const int i = threadIdx.x;
    __shared__ float xs[DIM];
    __shared__ float ts[DI];
    __shared__ float ps[DI];
    xs[i]       = d_xsum[n * DIM + i];
    xs[i + 128] = d_xsum[n * DIM + 128 + i];
    __syncthreads();

    float dt = 0.f, dp = 0.f;
    const float* wt = w_theta + (size_t)i * DIM;
    const float* wp = w_phi   + (size_t)i * DIM;
#pragma unroll 4
    for (int k = 0; k < DIM; ++k) {
        float xv = xs[k];
        dt = fmaf(wt[k], xv, dt);
        dp = fmaf(wp[k], xv, dp);
    }
    ts[i] = dt * (1.f / 16.f) + 256.f * b_theta[i];
    ps[i] = dp * (1.f / 16.f) + 256.f * b_phi[i];
    __syncthreads();

    const float sc = 0.08838834764831845f;
    float a = ts[i] * sc;
    float m = -1e30f;
#pragma unroll 4
    for (int j = 0; j < DI; ++j) m = fmaxf(m, a * ps[j]);
    float sum = 0.f;
#pragma unroll 4
    for (int j = 0; j < DI; ++j) sum += expf(a * ps[j] - m);
    float inv = 1.f / sum;

    float tbacc = 0.f;
    float* row = d_tp + ((size_t)n * DI + i) * DI;
#pragma unroll 4
    for (int j = 0; j < DI; ++j) {
        float e = expf(a * ps[j] - m) * inv;
        row[j] = e;
        tbacc = fmaf(e, b_g[j], tbacc);
    }
    d_tb[n * DI + i] = tbacc;
}

// ---------------------------------------------------------------------------
// small SIMT batched SGEMM for T and W2
// ---------------------------------------------------------------------------
template <int BM, int BN, int BK, int TM, int TN>
__global__ void sgemm_bias(const float* __restrict__ Aall, long long sA,
                           const float* __restrict__ Ball, long long sB,
                           float* __restrict__ Call, long long sC,
                           int M, int N, int K) {
    constexpr int THREADS = (BM / TM) * (BN / TN);
    const int b = blockIdx.z;
    const float* A = Aall + (long long)b * sA;
    const float* B = Ball + (long long)b * sB;
    float* C = Call + (long long)b * sC;

    __shared__ float As[BK][BM];
    __shared__ float Bs[BK][BN];

    const int tid  = threadIdx.x;
    const int tcol = tid % (BN / TN);
    const int trow = tid / (BN / TN);

    const float* Ag = A + (long long)blockIdx.y * BM * K;
    const float* Bg = B + blockIdx.x * BN;

    float acc[TM][TN];
#pragma unroll
    for (int i = 0; i < TM; ++i)
#pragma unroll
        for (int j = 0; j < TN; ++j) acc[i][j] = 0.f;

    for (int k0 = 0; k0 < K; k0 += BK) {
#pragma unroll
        for (int it = 0; it < (BM * BK) / (THREADS * 4); ++it) {
            int idx = (tid + it * THREADS) * 4;
            int r = idx / BK, c = idx % BK;
            float4 v = *(const float4*)(Ag + (long long)r * K + k0 + c);
            As[c + 0][r] = v.x; As[c + 1][r] = v.y;
            As[c + 2][r] = v.z; As[c + 3][r] = v.w;
        }
#pragma unroll
        for (int it = 0; it < (BK * BN) / (THREADS * 4); ++it) {
            int idx = (tid + it * THREADS) * 4;
            int r = idx / BN, c = idx % BN;
            *(float4*)(&Bs[r][c]) = *(const float4*)(Bg + (long long)(k0 + r) * N + c);
        }
        __syncthreads();

        float ar[TM], br[TN];
#pragma unroll
        for (int k = 0; k < BK; ++k) {
#pragma unroll
            for (int i = 0; i < TM; ++i) ar[i] = As[k][trow * TM + i];
#pragma unroll
            for (int j = 0; j < TN; ++j) br[j] = Bs[k][tcol * TN + j];
#pragma unroll
            for (int i = 0; i < TM; ++i)
#pragma unroll
                for (int j = 0; j < TN; ++j) acc[i][j] = fmaf(ar[i], br[j], acc[i][j]);
        }
        __syncthreads();
    }

#pragma unroll
    for (int i = 0; i < TM; ++i) {
        int row = blockIdx.y * BM + trow * TM + i;
        float* crow = C + (long long)row * N + blockIdx.x * BN + tcol * TN;
#pragma unroll
        for (int j = 0; j < TN; j += 4) {
            float4 v;
            v.x = acc[i][j + 0]; v.y = acc[i][j + 1];
            v.z = acc[i][j + 2]; v.w = acc[i][j + 3];
            *(float4*)(crow + j) = v;
        }
    }
}

// ---------------------------------------------------------------------------
// K4b: bias_p[n,c] = (w_out[c,:] . tb[n,:] + b_out[c]) * W2SCALE
// ---------------------------------------------------------------------------
__global__ void biasp_kernel(const float* __restrict__ w_out,
                             const float* __restrict__ b_out) {
    const int n = blockIdx.x;
    const int c = threadIdx.x;
    __shared__ float tbs[DI];
    if (c < DI) tbs[c] = d_tb[n * DI + c];
    __syncthreads();
    float d = 0.f;
    const float* wr = w_out + (size_t)c * DI;
#pragma unroll 4
    for (int j = 0; j < DI; ++j) d = fmaf(wr[j], tbs[j], d);
    d_biasp[n * DIM + c] = (d + b_out[c]) * W2SCALE;
}

// ---------------------------------------------------------------------------
// K5: split W2*256 fp32 -> fp16 hi/lo
// ---------------------------------------------------------------------------
__global__ void w2split_kernel() {
    const int n = blockIdx.x;
    const float* W = d_W2 + (size_t)n * 65536;
    __half* Hh = d_W2h + (size_t)n * 65536;
    __half* Hl = d_W2l + (size_t)n * 65536;
    for (int i = threadIdx.x; i < 65536; i += 256) {
        float v = W[i] * W2SCALE;
        __half h = __float2half_rn(v);
        __half l = __float2half_rn(v - __half2float(h));
        Hh[i] = h;
        Hl[i] = l;
    }
}

// ---------------------------------------------------------------------------
// K6: main tensor-core GEMM (fp16 2-product A-split), B via cp.async from
// pre-packed fp16 blob, A fragments via ldmatrix.x4. Fused BN stats epilogue,
// p written fp16.
// ---------------------------------------------------------------------------
#define AK    264                      // A smem row stride (fp16 units); 528 B
#define SM_AH 0
#define SM_AL (128*AK*2)               // 67584
#define SM_B  (2*128*AK*2)             // 135168
#define BROW  136                      // B smem kpair-row stride (u32 words); 544 B
#define BBUF  (32*BROW*4)              // 17408 bytes per buffer
#define GS    (SM_B + 2*BBUF)          // 169984 bytes

__device__ __forceinline__ void mma16816h(float* c, const uint32_t* a, const uint32_t* b) {
    asm volatile("mma.sync.aligned.m16n8k16.row.col.f32.f16.f16.f32 "
        "{%0,%1,%2,%3}, {%4,%5,%6,%7}, {%8,%9}, {%0,%1,%2,%3};"
        : "+f"(c[0]), "+f"(c[1]), "+f"(c[2]), "+f"(c[3])
        : "r"(a[0]), "r"(a[1]), "r"(a[2]), "r"(a[3]), "r"(b[0]), "r"(b[1]));
}

__device__ __forceinline__ void ldmx4(uint32_t* r, uint32_t addr) {
    asm volatile("ldmatrix.sync.aligned.m8n8.x4.shared.b16 {%0,%1,%2,%3}, [%4];"
        : "=r"(r[0]), "=r"(r[1]), "=r"(r[2]), "=r"(r[3]) : "r"(addr));
}

__global__ void __launch_bounds__(256, 1) mma_gemm() {
    extern __shared__ char smem[];
    const uint32_t sbase = smem_u32(smem);
    const int tid  = threadIdx.x;
    const int lane = tid & 31;
    const int wid  = tid >> 5;
    const int warp_m = wid >> 2;
    const int warp_n = wid & 3;
    const int bid = blockIdx.x;
    const int m = bid & 1, hwt = (bid >> 1) & 31, n = bid >> 6;

    // ---- load A (W2 hi/lo fp16) into padded smem ----
    {
        const uint4* gh = (const uint4*)(d_W2h + ((size_t)n * 256 + m * 128) * 256);
        const uint4* gl = (const uint4*)(d_W2l + ((size_t)n * 256 + m * 128) * 256);
#pragma unroll
        for (int i = 0; i < 16; ++i) {
            int idx = i * 256 + tid;
            int r = idx >> 5, c = idx & 31;
            *(uint4*)(smem + SM_AH + r * (AK * 2) + c * 16) = gh[idx];
            *(uint4*)(smem + SM_AL + r * (AK * 2) + c * 16) = gl[idx];
        }
    }

    float acc[4][4][4];
#pragma unroll
    for (int a = 0; a < 4; ++a)
#pragma unroll
        for (int b = 0; b < 4; ++b)
#pragma unroll
            for (int r = 0; r < 4; ++r) acc[a][b][r] = 0.f;

    const uint32_t* xsrc = d_xh + ((size_t)(n * 32 + hwt) * 128) * 128; // u32

    // issue cp.async for B chunk c into buffer c&1
    const int kp_ = tid >> 3;            // 0..31 (one kp row per 8 threads)
    const int ch8_ = (tid & 7) * 4;      // 4 x 16B chunks per thread
    {
        // chunk 0
        uint32_t dstb = sbase + SM_B;
#pragma unroll
        for (int q = 0; q < 4; ++q) {
            uint32_t dsm = dstb + kp_ * 544 + (ch8_ + q) * 16;
            const void* g = xsrc + kp_ * 128 + (ch8_ + q) * 4;
            asm volatile("cp.async.cg.shared.global [%0], [%1], 16;" :: "r"(dsm), "l"(g));
        }
        asm volatile("cp.async.commit_group;" ::: "memory");
    }

    for (int c = 0; c < 4; ++c) {
        const uint32_t b_base = SM_B + (c & 1) * BBUF;

        if (c < 3) {
            uint32_t dstb = sbase + SM_B + ((c + 1) & 1) * BBUF;
            const uint32_t* s = xsrc + (size_t)(c + 1) * 32 * 128;
#pragma unroll
            for (int q = 0; q < 4; ++q) {
                uint32_t dsm = dstb + kp_ * 544 + (ch8_ + q) * 16;
                const void* g = s + kp_ * 128 + (ch8_ + q) * 4;
                asm volatile("cp.async.cg.shared.global [%0], [%1], 16;" :: "r"(dsm), "l"(g));
            }
            asm volatile("cp.async.commit_group;" ::: "memory");
            asm volatile("cp.async.wait_group 1;" ::: "memory");
        } else {
            asm volatile("cp.async.wait_group 0;" ::: "memory");
        }
        __syncthreads();   // B chunk c visible to all; also covers A stores (c==0)

        // ---- compute: 4 k16 steps ----
#pragma unroll
        for (int ks = 0; ks < 4; ++ks) {
            const int k0c = c * 64 + ks * 16;
            // ldmatrix lane address pieces
            const int lrow = (lane & 7) + ((lane >> 3) & 1) * 8;
            const int lkof = (lane >> 4) * 8;
            uint32_t ah[4][4], al[4][4];
#pragma unroll
            for (int mf = 0; mf < 4; ++mf) {
                int r0 = warp_m * 64 + mf * 16 + lrow;
                uint32_t off = (uint32_t)(r0 * (AK * 2) + (k0c + lkof) * 2);
                ldmx4(ah[mf], sbase + SM_AH + off);
                ldmx4(al[mf], sbase + SM_AL + off);
            }
            uint32_t bb[4][2];
            const int kp0 = ks * 8 + (lane & 3);
#pragma unroll
            for (int nf = 0; nf < 4; ++nf) {
                int col = warp_n * 32 + nf * 8 + (lane >> 2);
                bb[nf][0] = *(const uint32_t*)(smem + b_base + (kp0 * BROW + col) * 4);
                bb[nf][1] = *(const uint32_t*)(smem + b_base + ((kp0 + 4) * BROW + col) * 4);
            }
#pragma unroll
            for (int mf = 0; mf < 4; ++mf)
#pragma unroll
                for (int nf = 0; nf < 4; ++nf) {
                    mma16816h(acc[mf][nf], ah[mf], bb[nf]);
                    mma16816h(acc[mf][nf], al[mf], bb[nf]);
                }
        }
        __syncthreads();   // all reads of this buffer done before it is refilled
    }

    // ---- epilogue: p = acc + bias (fp16 out); fused per-channel stats ----
    float* racc = (float*)(smem + SM_B);
    racc[tid] = 0.f;
    __syncthreads();

    const int colbase = warp_n * 32 + (lane & 3) * 2;
    __half* pg = d_ph + ((size_t)n * 256 + m * 128) * 4096 + hwt * 128;
    const float* biasg = d_biasp + n * 256 + m * 128;
#pragma unroll
    for (int mf = 0; mf < 4; ++mf) {
#pragma unroll
        for (int half = 0; half < 2; ++half) {
            int row = warp_m * 64 + mf * 16 + (lane >> 2) + half * 8;
            float bias = biasg[row];
            float s = 0.f, s2 = 0.f;
#pragma unroll
            for (int nf = 0; nf < 4; ++nf) {
                float v0 = acc[mf][nf][half * 2 + 0] + bias;
                float v1 = acc[mf][nf][half * 2 + 1] + bias;
                s += v0 + v1;
                s2 += v0 * v0 + v1 * v1;
                *(__half2*)(pg + (size_t)row * 4096 + nf * 8 + colbase) =
                    __floats2half2_rn(v0, v1);
            }
            s  += __shfl_xor_sync(0xffffffffu, s, 1);
            s  += __shfl_xor_sync(0xffffffffu, s, 2);
            s2 += __shfl_xor_sync(0xffffffffu, s2, 1);
            s2 += __shfl_xor_sync(0xffffffffu, s2, 2);
            if ((lane & 3) == 0) {
                atomicAdd(&racc[row * 2],     s);
                atomicAdd(&racc[row * 2 + 1], s2);
            }
        }
    }
    __syncthreads();
    if (tid < 128) {
        atomicAdd(&d_chsum[m * 128 + tid],   racc[tid * 2]);
        atomicAdd(&d_chsumsq[m * 128 + tid], racc[tid * 2 + 1]);
    }
}

// ---------------------------------------------------------------------------
// K7: finalize BN scale/shift (p scaled by W2SCALE; eps scaled to match)
// ---------------------------------------------------------------------------
__global__ void finalize_kernel(const float* __restrict__ gamma,
                                const float* __restrict__ beta) {
    int c = threadIdx.x;
    const float inv_cnt = 1.f / (float)CNT;
    float mean = d_chsum[c] * inv_cnt;
    float var  = d_chsumsq[c] * inv_cnt - mean * mean;
    float a = gamma[c] * rsqrtf(var + 1e-5f * W2SCALE * W2SCALE);
    d_scale[c] = a;
    d_shift[c] = beta[c] - a * mean;
}

// ---------------------------------------------------------------------------
// K8: out = x + scale[c]*p + shift[c]   (p fp16)
// ---------------------------------------------------------------------------
__global__ void out_kernel(const float* __restrict__ x, float* __restrict__ out) {
    size_t gid = (size_t)blockIdx.x * 256 + threadIdx.x;  // float4 index
    int c = (int)((gid >> 10) & 255);
    float a = d_scale[c], b = d_shift[c];
    float4 xv = ((const float4*)x)[gid];
    uint2 pw = ((const uint2*)d_ph)[gid];
    float2 p01 = __half22float2(*(__half2*)&pw.x);
    float2 p23 = __half22float2(*(__half2*)&pw.y);
    float4 o;
    o.x = fmaf(a, p01.x, xv.x + b);
    o.y = fmaf(a, p01.y, xv.y + b);
    o.z = fmaf(a, p23.x, xv.z + b);
    o.w = fmaf(a, p23.y, xv.w + b);
    ((float4*)out)[gid] = o;
}

// ---------------------------------------------------------------------------
// launch
// ---------------------------------------------------------------------------
extern "C" void kernel_launch(void* const* d_in, const int* in_sizes, int n_in,
                              void* d_out, int out_size) {
    const float* x       = (const float*)d_in[0];
    const float* w_theta = (const float*)d_in[1];
    const float* b_theta = (const float*)d_in[2];
    const float* w_phi   = (const float*)d_in[3];
    const float* b_phi   = (const float*)d_in[4];
    const float* w_g     = (const float*)d_in[5];
    const float* b_g     = (const float*)d_in[6];
    const float* w_out   = (const float*)d_in[7];
    const float* b_out   = (const float*)d_in[8];
    const float* gamma   = (const float*)d_in[9];
    const float* beta    = (const float*)d_in[10];
    float* out = (float*)d_out;
    (void)in_sizes; (void)n_in; (void)out_size;

    float *p_tp, *p_T, *p_W2;
    cudaGetSymbolAddress((void**)&p_tp, d_tp);
    cudaGetSymbolAddress((void**)&p_T,  d_T);
    cudaGetSymbolAddress((void**)&p_W2, d_W2);

    cudaFuncSetAttribute(mma_gemm, cudaFuncAttributeMaxDynamicSharedMemorySize, GS);

    zero_stats_kernel<<<1, 256>>>();
    cvtxsum_kernel<<<dim3(128, 32), 256>>>(x);
    attn_kernel<<<NB, 128>>>(w_theta, b_theta, w_phi, b_phi, b_g);

    // T[n] = tp[n] @ w_g : [128,256], K=128
    sgemm_bias<64, 64, 16, 4, 4><<<dim3(4, 2, NB), 256>>>(
        p_tp, (long long)DI * DI, w_g, 0, p_T, (long long)DI * DIM, DI, DIM, DI);
    // W2[n] = w_out @ T[n] : [256,256], K=128
    sgemm_bias<64, 64, 16, 4, 4><<<dim3(4, 4, NB), 256>>>(
        w_out, 0, p_T, (long long)DI * DIM, p_W2, (long long)DIM * DIM, DIM, DIM, DI);

    biasp_kernel<<<NB, 256>>>(w_out, b_out);
    w2split_kernel<<<NB, 256>>>();

    mma_gemm<<<2048, 256, GS>>>();

    finalize_kernel<<<1, 256>>>(gamma, beta);
    out_kernel<<<(size_t)NB * DIM * HW / 4 / 256, 256>>>(x, out);
}

// round 7
// speedup vs baseline: 1.7895x; 1.2148x over previous
#include <cuda_runtime.h>
#include <cuda_bf16.h>
#include <cuda_fp16.h>
#include <math.h>
#include <stdint.h>

#define NB   32
#define DIM  256
#define DI   128
#define HW   4096
#define CNT  (NB*HW)
#define W2SCALE 256.0f   // scale W2 & bias_p; BN normalization cancels it exactly

// ---------------------------------------------------------------------------
// Device scratch
// ---------------------------------------------------------------------------
__device__ float  d_xsum[NB*DIM];
__device__ float  d_tp[NB*DI*DI];
__device__ float  d_tb[NB*DI];
__device__ float  d_T[NB*DI*DIM];
__device__ float  d_W2[NB*DIM*DIM];
__device__ float  d_biasp[NB*DIM];
__device__ __half d_W2h[(size_t)NB*DIM*DIM];
// x in fp16, k-pair packed: [n][hwt(32)][kp(128)][hw(128)] u32 = (k=2kp lo, 2kp+1 hi)
__device__ uint32_t d_xh[(size_t)NB*32*128*128];   // 67 MB
__device__ __half d_ph[(size_t)NB*DIM*HW];          // pre-BN p (scaled x256), 67 MB
__device__ float  d_chsum[DIM];
__device__ float  d_chsumsq[DIM];
__device__ float  d_scale[DIM];
__device__ float  d_shift[DIM];

__device__ __forceinline__ uint32_t smem_u32(const void* p) {
    uint32_t a;
    asm("{ .reg .u64 t; cvta.to.shared.u64 t, %1; cvt.u32.u64 %0, t; }" : "=r"(a) : "l"(p));
    return a;
}

// ---------------------------------------------------------------------------
// K0: zero BN accumulators
// ---------------------------------------------------------------------------
__global__ void zero_stats_kernel() {
    int t = threadIdx.x;
    d_chsum[t] = 0.f;
    d_chsumsq[t] = 0.f;
}

// ---------------------------------------------------------------------------
// K1: convert x -> packed fp16 blob + per-(n,c) channel sums
// ---------------------------------------------------------------------------
__global__ void cvtxsum_kernel(const float* __restrict__ x) {
    const int kp = blockIdx.x, n = blockIdx.y, tid = threadIdx.x;
    const float4* r0 = (const float4*)(x + ((size_t)(n * 256 + 2 * kp)) * 4096);
    const float4* r1 = r0 + 1024;
    uint4* dst = (uint4*)d_xh;
    float s0 = 0.f, s1 = 0.f;
#pragma unroll
    for (int it = 0; it < 4; ++it) {
        int f4 = it * 256 + tid;
        float4 a = r0[f4];
        float4 b = r1[f4];
        s0 += a.x + a.y + a.z + a.w;
        s1 += b.x + b.y + b.z + b.w;
        __half2 h0 = __floats2half2_rn(a.x, b.x);
        __half2 h1 = __floats2half2_rn(a.y, b.y);
        __half2 h2 = __floats2half2_rn(a.z, b.z);
        __half2 h3 = __floats2half2_rn(a.w, b.w);
        uint4 w;
        w.x = *(uint32_t*)&h0; w.y = *(uint32_t*)&h1;
        w.z = *(uint32_t*)&h2; w.w = *(uint32_t*)&h3;
        int hwt = f4 >> 5;
        dst[(((size_t)(n * 32 + hwt) * 128 + kp) * 32) + (f4 & 31)] = w;
    }
#pragma unroll
    for (int o = 16; o; o >>= 1) {
        s0 += __shfl_down_sync(0xffffffffu, s0, o);
        s1 += __shfl_down_sync(0xffffffffu, s1, o);
    }
    __shared__ float w0[8], w1[8];
    if ((tid & 31) == 0) { w0[tid >> 5] = s0; w1[tid >> 5] = s1; }
    __syncthreads();
    if (tid < 8) {
        s0 = w0[tid]; s1 = w1[tid];
#pragma unroll
        for (int o = 4; o; o >>= 1) {
            s0 += __shfl_down_sync(0xffu, s0, o);
            s1 += __shfl_down_sync(0xffu, s1, o);
        }
        if (tid == 0) {
            d_xsum[n * 256 + 2 * kp]     = s0;
            d_xsum[n * 256 + 2 * kp + 1] = s1;
        }
    }
}

// ---------------------------------------------------------------------------
// K2: attention prep
// ---------------------------------------------------------------------------
__global__ void attn_kernel(const float* __restrict__ w_theta,
                            const float* __restrict__ b_theta,
                            const float* __restrict__ w_phi,
                            const float* __restrict__ b_phi,
                            const float* __restrict__ b_g) {
    const int n = blockIdx.x;
    const int i = threadIdx.x;
    __shared__ float xs[DIM];
    __shared__ float ts[DI];
    __shared__ float ps[DI];
    xs[i]       = d_xsum[n * DIM + i];
    xs[i + 128] = d_xsum[n * DIM + 128 + i];
    __syncthreads();

    float dt = 0.f, dp = 0.f;
    const float* wt = w_theta + (size_t)i * DIM;
    const float* wp = w_phi   + (size_t)i * DIM;
#pragma unroll 4
    for (int k = 0; k < DIM; ++k) {
        float xv = xs[k];
        dt = fmaf(wt[k], xv, dt);
        dp = fmaf(wp[k], xv, dp);
    }
    ts[i] = dt * (1.f / 16.f) + 256.f * b_theta[i];
    ps[i] = dp * (1.f / 16.f) + 256.f * b_phi[i];
    __syncthreads();

    const float sc = 0.08838834764831845f;
    float a = ts[i] * sc;
    float m = -1e30f;
#pragma unroll 4
    for (int j = 0; j < DI; ++j) m = fmaxf(m, a * ps[j]);
    float sum = 0.f;
#pragma unroll 4
    for (int j = 0; j < DI; ++j) sum += expf(a * ps[j] - m);
    float inv = 1.f / sum;

    float tbacc = 0.f;
    float* row = d_tp + ((size_t)n * DI + i) * DI;
#pragma unroll 4
    for (int j = 0; j < DI; ++j) {
        float e = expf(a * ps[j] - m) * inv;
        row[j] = e;
        tbacc = fmaf(e, b_g[j], tbacc);
    }
    d_tb[n * DI + i] = tbacc;
}

// ---------------------------------------------------------------------------
// small SIMT batched SGEMM for T and W2
// ---------------------------------------------------------------------------
template <int BM, int BN, int BK, int TM, int TN>
__global__ void sgemm_bias(const float* __restrict__ Aall, long long sA,
                           const float* __restrict__ Ball, long long sB,
                           float* __restrict__ Call, long long sC,
                           int M, int N, int K) {
    constexpr int THREADS = (BM / TM) * (BN / TN);
    const int b = blockIdx.z;
    const float* A = Aall + (long long)b * sA;
    const float* B = Ball + (long long)b * sB;
    float* C = Call + (long long)b * sC;

    __shared__ float As[BK][BM];
    __shared__ float Bs[BK][BN];

    const int tid  = threadIdx.x;
    const int tcol = tid % (BN / TN);
    const int trow = tid / (BN / TN);

    const float* Ag = A + (long long)blockIdx.y * BM * K;
    const float* Bg = B + blockIdx.x * BN;

    float acc[TM][TN];
#pragma unroll
    for (int i = 0; i < TM; ++i)
#pragma unroll
        for (int j = 0; j < TN; ++j) acc[i][j] = 0.f;

    for (int k0 = 0; k0 < K; k0 += BK) {
#pragma unroll
        for (int it = 0; it < (BM * BK) / (THREADS * 4); ++it) {
            int idx = (tid + it * THREADS) * 4;
            int r = idx / BK, c = idx % BK;
            float4 v = *(const float4*)(Ag + (long long)r * K + k0 + c);
            As[c + 0][r] = v.x; As[c + 1][r] = v.y;
            As[c + 2][r] = v.z; As[c + 3][r] = v.w;
        }
#pragma unroll
        for (int it = 0; it < (BK * BN) / (THREADS * 4); ++it) {
            int idx = (tid + it * THREADS) * 4;
            int r = idx / BN, c = idx % BN;
            *(float4*)(&Bs[r][c]) = *(const float4*)(Bg + (long long)(k0 + r) * N + c);
        }
        __syncthreads();

        float ar[TM], br[TN];
#pragma unroll
        for (int k = 0; k < BK; ++k) {
#pragma unroll
            for (int i = 0; i < TM; ++i) ar[i] = As[k][trow * TM + i];
#pragma unroll
            for (int j = 0; j < TN; ++j) br[j] = Bs[k][tcol * TN + j];
#pragma unroll
            for (int i = 0; i < TM; ++i)
#pragma unroll
                for (int j = 0; j < TN; ++j) acc[i][j] = fmaf(ar[i], br[j], acc[i][j]);
        }
        __syncthreads();
    }

#pragma unroll
    for (int i = 0; i < TM; ++i) {
        int row = blockIdx.y * BM + trow * TM + i;
        float* crow = C + (long long)row * N + blockIdx.x * BN + tcol * TN;
#pragma unroll
        for (int j = 0; j < TN; j += 4) {
            float4 v;
            v.x = acc[i][j + 0]; v.y = acc[i][j + 1];
            v.z = acc[i][j + 2]; v.w = acc[i][j + 3];
            *(float4*)(crow + j) = v;
        }
    }
}

// ---------------------------------------------------------------------------
// K4b: bias_p[n,c] = (w_out[c,:] . tb[n,:] + b_out[c]) * W2SCALE
// ---------------------------------------------------------------------------
__global__ void biasp_kernel(const float* __restrict__ w_out,
                             const float* __restrict__ b_out) {
    const int n = blockIdx.x;
    const int c = threadIdx.x;
    __shared__ float tbs[DI];
    if (c < DI) tbs[c] = d_tb[n * DI + c];
    __syncthreads();
    float d = 0.f;
    const float* wr = w_out + (size_t)c * DI;
#pragma unroll 4
    for (int j = 0; j < DI; ++j) d = fmaf(wr[j], tbs[j], d);
    d_biasp[n * DIM + c] = (d + b_out[c]) * W2SCALE;
}

// ---------------------------------------------------------------------------
// K5: convert W2*256 fp32 -> fp16 (single precision level now)
// ---------------------------------------------------------------------------
__global__ void w2cvt_kernel() {
    const int n = blockIdx.x;
    const float* W = d_W2 + (size_t)n * 65536;
    __half* Hh = d_W2h + (size_t)n * 65536;
    for (int i = threadIdx.x; i < 65536; i += 256)
        Hh[i] = __float2half_rn(W[i] * W2SCALE);
}

// ---------------------------------------------------------------------------
// K6: main tensor-core GEMM (single fp16 product), B via cp.async, A via
// ldmatrix. smem = 102.4KB -> 2 CTAs/SM. Fused BN stats; p written fp16.
// ---------------------------------------------------------------------------
#define AK    264                      // A smem row stride (fp16 units); 528 B
#define SM_A  0
#define SM_B  (128*AK*2)               // 67584
#define BROW  136                      // B smem kpair-row stride (u32 words); 544 B
#define BBUF  (32*BROW*4)              // 17408 bytes per buffer
#define GS    (SM_B + 2*BBUF)          // 102400 bytes

__device__ __forceinline__ void mma16816h(float* c, const uint32_t* a, const uint32_t* b) {
    asm volatile("mma.sync.aligned.m16n8k16.row.col.f32.f16.f16.f32 "
        "{%0,%1,%2,%3}, {%4,%5,%6,%7}, {%8,%9}, {%0,%1,%2,%3};"
        : "+f"(c[0]), "+f"(c[1]), "+f"(c[2]), "+f"(c[3])
        : "r"(a[0]), "r"(a[1]), "r"(a[2]), "r"(a[3]), "r"(b[0]), "r"(b[1]));
}

__device__ __forceinline__ void ldmx4(uint32_t* r, uint32_t addr) {
    asm volatile("ldmatrix.sync.aligned.m8n8.x4.shared.b16 {%0,%1,%2,%3}, [%4];"
        : "=r"(r[0]), "=r"(r[1]), "=r"(r[2]), "=r"(r[3]) : "r"(addr));
}

__global__ void __launch_bounds__(256, 2) mma_gemm() {
    extern __shared__ char smem[];
    const uint32_t sbase = smem_u32(smem);
    const int tid  = threadIdx.x;
    const int lane = tid & 31;
    const int wid  = tid >> 5;
    const int warp_m = wid >> 2;
    const int warp_n = wid & 3;
    const int bid = blockIdx.x;
    const int m = bid & 1, hwt = (bid >> 1) & 31, n = bid >> 6;

    // ---- load A (W2 fp16) into padded smem ----
    {
        const uint4* gh = (const uint4*)(d_W2h + ((size_t)n * 256 + m * 128) * 256);
#pragma unroll
        for (int i = 0; i < 16; ++i) {
            int idx = i * 256 + tid;
            int r = idx >> 5, c = idx & 31;
            *(uint4*)(smem + SM_A + r * (AK * 2) + c * 16) = gh[idx];
        }
    }

    float acc[4][4][4];
#pragma unroll
    for (int a = 0; a < 4; ++a)
#pragma unroll
        for (int b = 0; b < 4; ++b)
#pragma unroll
            for (int r = 0; r < 4; ++r) acc[a][b][r] = 0.f;

    const uint32_t* xsrc = d_xh + ((size_t)(n * 32 + hwt) * 128) * 128;

    const int kp_ = tid >> 3;
    const int ch8_ = (tid & 7) * 4;
    {
        uint32_t dstb = sbase + SM_B;
#pragma unroll
        for (int q = 0; q < 4; ++q) {
            uint32_t dsm = dstb + kp_ * 544 + (ch8_ + q) * 16;
            const void* g = xsrc + kp_ * 128 + (ch8_ + q) * 4;
            asm volatile("cp.async.cg.shared.global [%0], [%1], 16;" :: "r"(dsm), "l"(g));
        }
        asm volatile("cp.async.commit_group;" ::: "memory");
    }

    for (int c = 0; c < 4; ++c) {
        const uint32_t b_base = SM_B + (c & 1) * BBUF;

        if (c < 3) {
            uint32_t dstb = sbase + SM_B + ((c + 1) & 1) * BBUF;
            const uint32_t* s = xsrc + (size_t)(c + 1) * 32 * 128;
#pragma unroll
            for (int q = 0; q < 4; ++q) {
                uint32_t dsm = dstb + kp_ * 544 + (ch8_ + q) * 16;
                const void* g = s + kp_ * 128 + (ch8_ + q) * 4;
                asm volatile("cp.async.cg.shared.global [%0], [%1], 16;" :: "r"(dsm), "l"(g));
            }
            asm volatile("cp.async.commit_group;" ::: "memory");
            asm volatile("cp.async.wait_group 1;" ::: "memory");
        } else {
            asm volatile("cp.async.wait_group 0;" ::: "memory");
        }
        __syncthreads();

#pragma unroll
        for (int ks = 0; ks < 4; ++ks) {
            const int k0c = c * 64 + ks * 16;
            const int lrow = (lane & 7) + ((lane >> 3) & 1) * 8;
            const int lkof = (lane >> 4) * 8;
            uint32_t ah[4][4];
#pragma unroll
            for (int mf = 0; mf < 4; ++mf) {
                int r0 = warp_m * 64 + mf * 16 + lrow;
                uint32_t off = (uint32_t)(r0 * (AK * 2) + (k0c + lkof) * 2);
                ldmx4(ah[mf], sbase + SM_A + off);
            }
            uint32_t bb[4][2];
            const int kp0 = ks * 8 + (lane & 3);
#pragma unroll
            for (int nf = 0; nf < 4; ++nf) {
                int col = warp_n * 32 + nf * 8 + (lane >> 2);
                bb[nf][0] = *(const uint32_t*)(smem + b_base + (kp0 * BROW + col) * 4);
                bb[nf][1] = *(const uint32_t*)(smem + b_base + ((kp0 + 4) * BROW + col) * 4);
            }
#pragma unroll
            for (int mf = 0; mf < 4; ++mf)
#pragma unroll
                for (int nf = 0; nf < 4; ++nf)
                    mma16816h(acc[mf][nf], ah[mf], bb[nf]);
        }
        __syncthreads();
    }

    // ---- epilogue: p = acc + bias (fp16 out); fused per-channel stats ----
    float* racc = (float*)(smem + SM_B);
    racc[tid] = 0.f;
    __syncthreads();

    const int colbase = warp_n * 32 + (lane & 3) * 2;
    __half* pg = d_ph + ((size_t)n * 256 + m * 128) * 4096 + hwt * 128;
    const float* biasg = d_biasp + n * 256 + m * 128;
#pragma unroll
    for (int mf = 0; mf < 4; ++mf) {
#pragma unroll
        for (int half = 0; half < 2; ++half) {
            int row = warp_m * 64 + mf * 16 + (lane >> 2) + half * 8;
            float bias = biasg[row];
            float s = 0.f, s2 = 0.f;
#pragma unroll
            for (int nf = 0; nf < 4; ++nf) {
                float v0 = acc[mf][nf][half * 2 + 0] + bias;
                float v1 = acc[mf][nf][half * 2 + 1] + bias;
                s += v0 + v1;
                s2 += v0 * v0 + v1 * v1;
                *(__half2*)(pg + (size_t)row * 4096 + nf * 8 + colbase) =
                    __floats2half2_rn(v0, v1);
            }
            s  += __shfl_xor_sync(0xffffffffu, s, 1);
            s  += __shfl_xor_sync(0xffffffffu, s, 2);
            s2 += __shfl_xor_sync(0xffffffffu, s2, 1);
            s2 += __shfl_xor_sync(0xffffffffu, s2, 2);
            if ((lane & 3) == 0) {
                atomicAdd(&racc[row * 2],     s);
                atomicAdd(&racc[row * 2 + 1], s2);
            }
        }
    }
    __syncthreads();
    if (tid < 128) {
        atomicAdd(&d_chsum[m * 128 + tid],   racc[tid * 2]);
        atomicAdd(&d_chsumsq[m * 128 + tid], racc[tid * 2 + 1]);
    }
}

// ---------------------------------------------------------------------------
// K7: finalize BN scale/shift (p scaled by W2SCALE; eps scaled to match)
// ---------------------------------------------------------------------------
__global__ void finalize_kernel(const float* __restrict__ gamma,
                                const float* __restrict__ beta) {
    int c = threadIdx.x;
    const float inv_cnt = 1.f / (float)CNT;
    float mean = d_chsum[c] * inv_cnt;
    float var  = d_chsumsq[c] * inv_cnt - mean * mean;
    float a = gamma[c] * rsqrtf(var + 1e-5f * W2SCALE * W2SCALE);
    d_scale[c] = a;
    d_shift[c] = beta[c] - a * mean;
}

// ---------------------------------------------------------------------------
// K8: out = x + scale[c]*p + shift[c]   (p fp16)
// ---------------------------------------------------------------------------
__global__ void out_kernel(const float* __restrict__ x, float* __restrict__ out) {
    size_t gid = (size_t)blockIdx.x * 256 + threadIdx.x;
    int c = (int)((gid >> 10) & 255);
    float a = d_scale[c], b = d_shift[c];
    float4 xv = ((const float4*)x)[gid];
    uint2 pw = ((const uint2*)d_ph)[gid];
    float2 p01 = __half22float2(*(__half2*)&pw.x);
    float2 p23 = __half22float2(*(__half2*)&pw.y);
    float4 o;
    o.x = fmaf(a, p01.x, xv.x + b);
    o.y = fmaf(a, p01.y, xv.y + b);
    o.z = fmaf(a, p23.x, xv.z + b);
    o.w = fmaf(a, p23.y, xv.w + b);
    ((float4*)out)[gid] = o;
}

// ---------------------------------------------------------------------------
// launch
// ---------------------------------------------------------------------------
extern "C" void kernel_launch(void* const* d_in, const int* in_sizes, int n_in,
                              void* d_out, int out_size) {
    const float* x       = (const float*)d_in[0];
    const float* w_theta = (const float*)d_in[1];
    const float* b_theta = (const float*)d_in[2];
    const float* w_phi   = (const float*)d_in[3];
    const float* b_phi   = (const float*)d_in[4];
    const float* w_g     = (const float*)d_in[5];
    const float* b_g     = (const float*)d_in[6];
    const float* w_out   = (const float*)d_in[7];
    const float* b_out   = (const float*)d_in[8];
    const float* gamma   = (const float*)d_in[9];
    const float* beta    = (const float*)d_in[10];
    float* out = (float*)d_out;
    (void)in_sizes; (void)n_in; (void)out_size;

    float *p_tp, *p_T, *p_W2;
    cudaGetSymbolAddress((void**)&p_tp, d_tp);
    cudaGetSymbolAddress((void**)&p_T,  d_T);
    cudaGetSymbolAddress((void**)&p_W2, d_W2);

    cudaFuncSetAttribute(mma_gemm, cudaFuncAttributeMaxDynamicSharedMemorySize, GS);

    zero_stats_kernel<<<1, 256>>>();
    cvtxsum_kernel<<<dim3(128, 32), 256>>>(x);
    attn_kernel<<<NB, 128>>>(w_theta, b_theta, w_phi, b_phi, b_g);

    // T[n] = tp[n] @ w_g : [128,256], K=128
    sgemm_bias<64, 64, 16, 4, 4><<<dim3(4, 2, NB), 256>>>(
        p_tp, (long long)DI * DI, w_g, 0, p_T, (long long)DI * DIM, DI, DIM, DI);
    // W2[n] = w_out @ T[n] : [256,256], K=128
    sgemm_bias<64, 64, 16, 4, 4><<<dim3(4, 4, NB), 256>>>(
        w_out, 0, p_T, (long long)DI * DIM, p_W2, (long long)DIM * DIM, DIM, DIM, DI);

    biasp_kernel<<<NB, 256>>>(w_out, b_out);
    w2cvt_kernel<<<NB, 256>>>();

    mma_gemm<<<2048, 256, GS>>>();

    finalize_kernel<<<1, 256>>>(gamma, beta);
    out_kernel<<<(size_t)NB * DIM * HW / 4 / 256, 256>>>(x, out);
}

// round 8
// speedup vs baseline: 2.2928x; 1.2812x over previous
#include <cuda_runtime.h>
#include <cuda_bf16.h>
#include <cuda_fp16.h>
#include <math.h>
#include <stdint.h>

#define NB   32
#define DIM  256
#define DI   128
#define HW   4096
#define CNT  (NB*HW)
#define W2SCALE 256.0f   // scale W2 & bias_p; BN normalization cancels it exactly

// ---------------------------------------------------------------------------
// Device scratch
// ---------------------------------------------------------------------------
__device__ float  d_xsum[NB*DIM];
__device__ float  d_tp[NB*DI*DI];
__device__ float  d_T[NB*DI*DIM];
__device__ float  d_biasp[NB*DIM];
__device__ __half d_W2h[(size_t)NB*DIM*DIM];
// x in fp16, k-pair packed: [n][hwt(32)][kp(128)][hw(128)] u32 = (k=2kp lo, 2kp+1 hi)
__device__ uint32_t d_xh[(size_t)NB*32*128*128];   // 67 MB
__device__ __half d_ph[(size_t)NB*DIM*HW];          // pre-BN p (scaled x256), 67 MB
__device__ float  d_chsum[DIM];
__device__ float  d_chsumsq[DIM];
__device__ float  d_scale[DIM];
__device__ float  d_shift[DIM];

__device__ __forceinline__ uint32_t smem_u32(const void* p) {
    uint32_t a;
    asm("{ .reg .u64 t; cvta.to.shared.u64 t, %1; cvt.u32.u64 %0, t; }" : "=r"(a) : "l"(p));
    return a;
}

// ---------------------------------------------------------------------------
// K0: zero BN accumulators
// ---------------------------------------------------------------------------
__global__ void zero_stats_kernel() {
    int t = threadIdx.x;
    d_chsum[t] = 0.f;
    d_chsumsq[t] = 0.f;
}

// ---------------------------------------------------------------------------
// K1: convert x -> packed fp16 blob + per-(n,c) channel sums
// ---------------------------------------------------------------------------
__global__ void cvtxsum_kernel(const float* __restrict__ x) {
    const int kp = blockIdx.x, n = blockIdx.y, tid = threadIdx.x;
    const float4* r0 = (const float4*)(x + ((size_t)(n * 256 + 2 * kp)) * 4096);
    const float4* r1 = r0 + 1024;
    uint4* dst = (uint4*)d_xh;
    float s0 = 0.f, s1 = 0.f;
#pragma unroll
    for (int it = 0; it < 4; ++it) {
        int f4 = it * 256 + tid;
        float4 a = r0[f4];
        float4 b = r1[f4];
        s0 += a.x + a.y + a.z + a.w;
        s1 += b.x + b.y + b.z + b.w;
        __half2 h0 = __floats2half2_rn(a.x, b.x);
        __half2 h1 = __floats2half2_rn(a.y, b.y);
        __half2 h2 = __floats2half2_rn(a.z, b.z);
        __half2 h3 = __floats2half2_rn(a.w, b.w);
        uint4 w;
        w.x = *(uint32_t*)&h0; w.y = *(uint32_t*)&h1;
        w.z = *(uint32_t*)&h2; w.w = *(uint32_t*)&h3;
        int hwt = f4 >> 5;
        dst[(((size_t)(n * 32 + hwt) * 128 + kp) * 32) + (f4 & 31)] = w;
    }
#pragma unroll
    for (int o = 16; o; o >>= 1) {
        s0 += __shfl_down_sync(0xffffffffu, s0, o);
        s1 += __shfl_down_sync(0xffffffffu, s1, o);
    }
    __shared__ float w0[8], w1[8];
    if ((tid & 31) == 0) { w0[tid >> 5] = s0; w1[tid >> 5] = s1; }
    __syncthreads();
    if (tid < 8) {
        s0 = w0[tid]; s1 = w1[tid];
#pragma unroll
        for (int o = 4; o; o >>= 1) {
            s0 += __shfl_down_sync(0xffu, s0, o);
            s1 += __shfl_down_sync(0xffu, s1, o);
        }
        if (tid == 0) {
            d_xsum[n * 256 + 2 * kp]     = s0;
            d_xsum[n * 256 + 2 * kp + 1] = s1;
        }
    }
}

// ---------------------------------------------------------------------------
// K2: attention prep + fused bias_p  (bias_p = (w_out.tb + b_out)*W2SCALE)
// ---------------------------------------------------------------------------
__global__ void attn_bias_kernel(const float* __restrict__ w_theta,
                                 const float* __restrict__ b_theta,
                                 const float* __restrict__ w_phi,
                                 const float* __restrict__ b_phi,
                                 const float* __restrict__ b_g,
                                 const float* __restrict__ w_out,
                                 const float* __restrict__ b_out) {
    const int n = blockIdx.x;
    const int i = threadIdx.x;
    __shared__ float xs[DIM];
    __shared__ float ts[DI];
    __shared__ float ps[DI];
    __shared__ float tbs[DI];
    xs[i]       = d_xsum[n * DIM + i];
    xs[i + 128] = d_xsum[n * DIM + 128 + i];
    __syncthreads();

    float dt = 0.f, dp = 0.f;
    const float* wt = w_theta + (size_t)i * DIM;
    const float* wp = w_phi   + (size_t)i * DIM;
#pragma unroll 4
    for (int k = 0; k < DIM; ++k) {
        float xv = xs[k];
        dt = fmaf(wt[k], xv, dt);
        dp = fmaf(wp[k], xv, dp);
    }
    ts[i] = dt * (1.f / 16.f) + 256.f * b_theta[i];
    ps[i] = dp * (1.f / 16.f) + 256.f * b_phi[i];
    __syncthreads();

    const float sc = 0.08838834764831845f;
    float a = ts[i] * sc;
    float m = -1e30f;
#pragma unroll 4
    for (int j = 0; j < DI; ++j) m = fmaxf(m, a * ps[j]);
    float sum = 0.f;
#pragma unroll 4
    for (int j = 0; j < DI; ++j) sum += expf(a * ps[j] - m);
    float inv = 1.f / sum;

    float tbacc = 0.f;
    float* row = d_tp + ((size_t)n * DI + i) * DI;
#pragma unroll 4
    for (int j = 0; j < DI; ++j) {
        float e = expf(a * ps[j] - m) * inv;
        row[j] = e;
        tbacc = fmaf(e, b_g[j], tbacc);
    }
    tbs[i] = tbacc;
    __syncthreads();

    // fused bias_p: each thread handles channels i and i+128
#pragma unroll
    for (int cc = 0; cc < 2; ++cc) {
        int c = i + cc * 128;
        float d = 0.f;
        const float* wr = w_out + (size_t)c * DI;
#pragma unroll 4
        for (int j = 0; j < DI; ++j) d = fmaf(wr[j], tbs[j], d);
        d_biasp[n * DIM + c] = (d + b_out[c]) * W2SCALE;
    }
}

// ---------------------------------------------------------------------------
// small SIMT batched SGEMM (fp32 out) for T
// ---------------------------------------------------------------------------
template <int BM, int BN, int BK, int TM, int TN>
__global__ void sgemm_bias(const float* __restrict__ Aall, long long sA,
                           const float* __restrict__ Ball, long long sB,
                           float* __restrict__ Call, long long sC,
                           int M, int N, int K) {
    constexpr int THREADS = (BM / TM) * (BN / TN);
    const int b = blockIdx.z;
    const float* A = Aall + (long long)b * sA;
    const float* B = Ball + (long long)b * sB;
    float* C = Call + (long long)b * sC;

    __shared__ float As[BK][BM];
    __shared__ float Bs[BK][BN];

    const int tid  = threadIdx.x;
    const int tcol = tid % (BN / TN);
    const int trow = tid / (BN / TN);

    const float* Ag = A + (long long)blockIdx.y * BM * K;
    const float* Bg = B + blockIdx.x * BN;

    float acc[TM][TN];
#pragma unroll
    for (int i = 0; i < TM; ++i)
#pragma unroll
        for (int j = 0; j < TN; ++j) acc[i][j] = 0.f;

    for (int k0 = 0; k0 < K; k0 += BK) {
#pragma unroll
        for (int it = 0; it < (BM * BK) / (THREADS * 4); ++it) {
            int idx = (tid + it * THREADS) * 4;
            int r = idx / BK, c = idx % BK;
            float4 v = *(const float4*)(Ag + (long long)r * K + k0 + c);
            As[c + 0][r] = v.x; As[c + 1][r] = v.y;
            As[c + 2][r] = v.z; As[c + 3][r] = v.w;
        }
#pragma unroll
        for (int it = 0; it < (BK * BN) / (THREADS * 4); ++it) {
            int idx = (tid + it * THREADS) * 4;
            int r = idx / BN, c = idx % BN;
            *(float4*)(&Bs[r][c]) = *(const float4*)(Bg + (long long)(k0 + r) * N + c);
        }
        __syncthreads();

        float ar[TM], br[TN];
#pragma unroll
        for (int k = 0; k < BK; ++k) {
#pragma unroll
            for (int i = 0; i < TM; ++i) ar[i] = As[k][trow * TM + i];
#pragma unroll
            for (int j = 0; j < TN; ++j) br[j] = Bs[k][tcol * TN + j];
#pragma unroll
            for (int i = 0; i < TM; ++i)
#pragma unroll
                for (int j = 0; j < TN; ++j) acc[i][j] = fmaf(ar[i], br[j], acc[i][j]);
        }
        __syncthreads();
    }

#pragma unroll
    for (int i = 0; i < TM; ++i) {
        int row = blockIdx.y * BM + trow * TM + i;
        float* crow = C + (long long)row * N + blockIdx.x * BN + tcol * TN;
#pragma unroll
        for (int j = 0; j < TN; j += 4) {
            float4 v;
            v.x = acc[i][j + 0]; v.y = acc[i][j + 1];
            v.z = acc[i][j + 2]; v.w = acc[i][j + 3];
            *(float4*)(crow + j) = v;
        }
    }
}

// ---------------------------------------------------------------------------
// sgemm variant writing scaled fp16 (W2h = (w_out @ T) * W2SCALE)
// ---------------------------------------------------------------------------
template <int BM, int BN, int BK, int TM, int TN>
__global__ void sgemm_f16(const float* __restrict__ Aall, long long sA,
                          const float* __restrict__ Ball, long long sB,
                          __half* __restrict__ Call, long long sC,
                          int M, int N, int K) {
    constexpr int THREADS = (BM / TM) * (BN / TN);
    const int b = blockIdx.z;
    const float* A = Aall + (long long)b * sA;
    const float* B = Ball + (long long)b * sB;
    __half* C = Call + (long long)b * sC;

    __shared__ float As[BK][BM];
    __shared__ float Bs[BK][BN];

    const int tid  = threadIdx.x;
    const int tcol = tid % (BN / TN);
    const int trow = tid / (BN / TN);

    const float* Ag = A + (long long)blockIdx.y * BM * K;
    const float* Bg = B + blockIdx.x * BN;

    float acc[TM][TN];
#pragma unroll
    for (int i = 0; i < TM; ++i)
#pragma unroll
        for (int j = 0; j < TN; ++j) acc[i][j] = 0.f;

    for (int k0 = 0; k0 < K; k0 += BK) {
#pragma unroll
        for (int it = 0; it < (BM * BK) / (THREADS * 4); ++it) {
            int idx = (tid + it * THREADS) * 4;
            int r = idx / BK, c = idx % BK;
            float4 v = *(const float4*)(Ag + (long long)r * K + k0 + c);
            As[c + 0][r] = v.x; As[c + 1][r] = v.y;
            As[c + 2][r] = v.z; As[c + 3][r] = v.w;
        }
#pragma unroll
        for (int it = 0; it < (BK * BN) / (THREADS * 4); ++it) {
            int idx = (tid + it * THREADS) * 4;
            int r = idx / BN, c = idx % BN;
            *(float4*)(&Bs[r][c]) = *(const float4*)(Bg + (long long)(k0 + r) * N + c);
        }
        __syncthreads();

        float ar[TM], br[TN];
#pragma unroll
        for (int k = 0; k < BK; ++k) {
#pragma unroll
            for (int i = 0; i < TM; ++i) ar[i] = As[k][trow * TM + i];
#pragma unroll
            for (int j = 0; j < TN; ++j) br[j] = Bs[k][tcol * TN + j];
#pragma unroll
            for (int i = 0; i < TM; ++i)
#pragma unroll
                for (int j = 0; j < TN; ++j) acc[i][j] = fmaf(ar[i], br[j], acc[i][j]);
        }
        __syncthreads();
    }

#pragma unroll
    for (int i = 0; i < TM; ++i) {
        int row = blockIdx.y * BM + trow * TM + i;
        __half* crow = C + (long long)row * N + blockIdx.x * BN + tcol * TN;
#pragma unroll
        for (int j = 0; j < TN; j += 4) {
            __half2 h01 = __floats2half2_rn(acc[i][j + 0] * W2SCALE, acc[i][j + 1] * W2SCALE);
            __half2 h23 = __floats2half2_rn(acc[i][j + 2] * W2SCALE, acc[i][j + 3] * W2SCALE);
            *(__half2*)(crow + j)     = h01;
            *(__half2*)(crow + j + 2) = h23;
        }
    }
}

// ---------------------------------------------------------------------------
// K6: main tensor-core GEMM — identical to R7 (profiling target this round)
// ---------------------------------------------------------------------------
#define AK    264                      // A smem row stride (fp16 units); 528 B
#define SM_A  0
#define SM_B  (128*AK*2)               // 67584
#define BROW  136                      // B smem kpair-row stride (u32 words); 544 B
#define BBUF  (32*BROW*4)              // 17408 bytes per buffer
#define GS    (SM_B + 2*BBUF)          // 102400 bytes

__device__ __forceinline__ void mma16816h(float* c, const uint32_t* a, const uint32_t* b) {
    asm volatile("mma.sync.aligned.m16n8k16.row.col.f32.f16.f16.f32 "
        "{%0,%1,%2,%3}, {%4,%5,%6,%7}, {%8,%9}, {%0,%1,%2,%3};"
        : "+f"(c[0]), "+f"(c[1]), "+f"(c[2]), "+f"(c[3])
        : "r"(a[0]), "r"(a[1]), "r"(a[2]), "r"(a[3]), "r"(b[0]), "r"(b[1]));
}

__device__ __forceinline__ void ldmx4(uint32_t* r, uint32_t addr) {
    asm volatile("ldmatrix.sync.aligned.m8n8.x4.shared.b16 {%0,%1,%2,%3}, [%4];"
        : "=r"(r[0]), "=r"(r[1]), "=r"(r[2]), "=r"(r[3]) : "r"(addr));
}

__global__ void __launch_bounds__(256, 2) mma_gemm() {
    extern __shared__ char smem[];
    const uint32_t sbase = smem_u32(smem);
    const int tid  = threadIdx.x;
    const int lane = tid & 31;
    const int wid  = tid >> 5;
    const int warp_m = wid >> 2;
    const int warp_n = wid & 3;
    const int bid = blockIdx.x;
    const int m = bid & 1, hwt = (bid >> 1) & 31, n = bid >> 6;

    {
        const uint4* gh = (const uint4*)(d_W2h + ((size_t)n * 256 + m * 128) * 256);
#pragma unroll
        for (int i = 0; i < 16; ++i) {
            int idx = i * 256 + tid;
            int r = idx >> 5, c = idx & 31;
            *(uint4*)(smem + SM_A + r * (AK * 2) + c * 16) = gh[idx];
        }
    }

    float acc[4][4][4];
#pragma unroll
    for (int a = 0; a < 4; ++a)
#pragma unroll
        for (int b = 0; b < 4; ++b)
#pragma unroll
            for (int r = 0; r < 4; ++r) acc[a][b][r] = 0.f;

    const uint32_t* xsrc = d_xh + ((size_t)(n * 32 + hwt) * 128) * 128;

    const int kp_ = tid >> 3;
    const int ch8_ = (tid & 7) * 4;
    {
        uint32_t dstb = sbase + SM_B;
#pragma unroll
        for (int q = 0; q < 4; ++q) {
            uint32_t dsm = dstb + kp_ * 544 + (ch8_ + q) * 16;
            const void* g = xsrc + kp_ * 128 + (ch8_ + q) * 4;
            asm volatile("cp.async.cg.shared.global [%0], [%1], 16;" :: "r"(dsm), "l"(g));
        }
        asm volatile("cp.async.commit_group;" ::: "memory");
    }

    for (int c = 0; c < 4; ++c) {
        const uint32_t b_base = SM_B + (c & 1) * BBUF;

        if (c < 3) {
            uint32_t dstb = sbase + SM_B + ((c + 1) & 1) * BBUF;
            const uint32_t* s = xsrc + (size_t)(c + 1) * 32 * 128;
#pragma unroll
            for (int q = 0; q < 4; ++q) {
                uint32_t dsm = dstb + kp_ * 544 + (ch8_ + q) * 16;
                const void* g = s + kp_ * 128 + (ch8_ + q) * 4;
                asm volatile("cp.async.cg.shared.global [%0], [%1], 16;" :: "r"(dsm), "l"(g));
            }
            asm volatile("cp.async.commit_group;" ::: "memory");
            asm volatile("cp.async.wait_group 1;" ::: "memory");
        } else {
            asm volatile("cp.async.wait_group 0;" ::: "memory");
        }
        __syncthreads();

#pragma unroll
        for (int ks = 0; ks < 4; ++ks) {
            const int k0c = c * 64 + ks * 16;
            const int lrow = (lane & 7) + ((lane >> 3) & 1) * 8;
            const int lkof = (lane >> 4) * 8;
            uint32_t ah[4][4];
#pragma unroll
            for (int mf = 0; mf < 4; ++mf) {
                int r0 = warp_m * 64 + mf * 16 + lrow;
                uint32_t off = (uint32_t)(r0 * (AK * 2) + (k0c + lkof) * 2);
                ldmx4(ah[mf], sbase + SM_A + off);
            }
            uint32_t bb[4][2];
            const int kp0 = ks * 8 + (lane & 3);
#pragma unroll
            for (int nf = 0; nf < 4; ++nf) {
                int col = warp_n * 32 + nf * 8 + (lane >> 2);
                bb[nf][0] = *(const uint32_t*)(smem + b_base + (kp0 * BROW + col) * 4);
                bb[nf][1] = *(const uint32_t*)(smem + b_base + ((kp0 + 4) * BROW + col) * 4);
            }
#pragma unroll
            for (int mf = 0; mf < 4; ++mf)
#pragma unroll
                for (int nf = 0; nf < 4; ++nf)
                    mma16816h(acc[mf][nf], ah[mf], bb[nf]);
        }
        __syncthreads();
    }

    float* racc = (float*)(smem + SM_B);
    racc[tid] = 0.f;
    __syncthreads();

    const int colbase = warp_n * 32 + (lane & 3) * 2;
    __half* pg = d_ph + ((size_t)n * 256 + m * 128) * 4096 + hwt * 128;
    const float* biasg = d_biasp + n * 256 + m * 128;
#pragma unroll
    for (int mf = 0; mf < 4; ++mf) {
#pragma unroll
        for (int half = 0; half < 2; ++half) {
            int row = warp_m * 64 + mf * 16 + (lane >> 2) + half * 8;
            float bias = biasg[row];
            float s = 0.f, s2 = 0.f;
#pragma unroll
            for (int nf = 0; nf < 4; ++nf) {
                float v0 = acc[mf][nf][half * 2 + 0] + bias;
                float v1 = acc[mf][nf][half * 2 + 1] + bias;
                s += v0 + v1;
                s2 += v0 * v0 + v1 * v1;
                *(__half2*)(pg + (size_t)row * 4096 + nf * 8 + colbase) =
                    __floats2half2_rn(v0, v1);
            }
            s  += __shfl_xor_sync(0xffffffffu, s, 1);
            s  += __shfl_xor_sync(0xffffffffu, s, 2);
            s2 += __shfl_xor_sync(0xffffffffu, s2, 1);
            s2 += __shfl_xor_sync(0xffffffffu, s2, 2);
            if ((lane & 3) == 0) {
                atomicAdd(&racc[row * 2],     s);
                atomicAdd(&racc[row * 2 + 1], s2);
            }
        }
    }
    __syncthreads();
    if (tid < 128) {
        atomicAdd(&d_chsum[m * 128 + tid],   racc[tid * 2]);
        atomicAdd(&d_chsumsq[m * 128 + tid], racc[tid * 2 + 1]);
    }
}

// ---------------------------------------------------------------------------
// K7: finalize BN scale/shift
// ---------------------------------------------------------------------------
__global__ void finalize_kernel(const float* __restrict__ gamma,
                                const float* __restrict__ beta) {
    int c = threadIdx.x;
    const float inv_cnt = 1.f / (float)CNT;
    float mean = d_chsum[c] * inv_cnt;
    float var  = d_chsumsq[c] * inv_cnt - mean * mean;
    float a = gamma[c] * rsqrtf(var + 1e-5f * W2SCALE * W2SCALE);
    d_scale[c] = a;
    d_shift[c] = beta[c] - a * mean;
}

// ---------------------------------------------------------------------------
// K8: out = x + scale*p + shift, reading fp16 xh (residual) and fp16 p.
// Each thread: one (n,hwt,kp) group, 4 hw positions, 2 channels (2kp, 2kp+1).
// ---------------------------------------------------------------------------
__global__ void out2_kernel(float* __restrict__ out) {
    const size_t g = ((size_t)blockIdx.x * 256 + threadIdx.x) * 4; // u32 index into d_xh
    const int hw32 = (int)(g & 127);
    const int kp   = (int)((g >> 7) & 127);
    const int hwt  = (int)((g >> 14) & 31);
    const int n    = (int)(g >> 19);
    const int c0 = 2 * kp, c1 = c0 + 1;

    const float a0 = d_scale[c0], b0 = d_shift[c0];
    const float a1 = d_scale[c1], b1 = d_shift[c1];

    uint4 xw = *(const uint4*)(d_xh + g);
    const size_t hwg = (size_t)hwt * 128 + hw32;
    uint2 p0 = *(const uint2*)(d_ph + ((size_t)(n * 256 + c0)) * 4096 + hwg);
    uint2 p1 = *(const uint2*)(d_ph + ((size_t)(n * 256 + c1)) * 4096 + hwg);

    float2 x0a = __half22float2(*(__half2*)&xw.x);  // (c0, c1) at hw+0
    float2 x0b = __half22float2(*(__half2*)&xw.y);
    float2 x0c = __half22float2(*(__half2*)&xw.z);
    float2 x0d = __half22float2(*(__half2*)&xw.w);
    float2 p0a = __half22float2(*(__half2*)&p0.x);  // c0 at hw+0, hw+1
    float2 p0b = __half22float2(*(__half2*)&p0.y);
    float2 p1a = __half22float2(*(__half2*)&p1.x);
    float2 p1b = __half22float2(*(__half2*)&p1.y);

    float4 o0, o1;
    o0.x = fmaf(a0, p0a.x, x0a.x + b0);
    o0.y = fmaf(a0, p0a.y, x0b.x + b0);
    o0.z = fmaf(a0, p0b.x, x0c.x + b0);
    o0.w = fmaf(a0, p0b.y, x0d.x + b0);
    o1.x = fmaf(a1, p1a.x, x0a.y + b1);
    o1.y = fmaf(a1, p1a.y, x0b.y + b1);
    o1.z = fmaf(a1, p1b.x, x0c.y + b1);
    o1.w = fmaf(a1, p1b.y, x0d.y + b1);

    *(float4*)(out + ((size_t)(n * 256 + c0)) * 4096 + hwg) = o0;
    *(float4*)(out + ((size_t)(n * 256 + c1)) * 4096 + hwg) = o1;
}

// ---------------------------------------------------------------------------
// launch — order matters: mma_gemm is launch index 5 (ncu -s 5 -c 1 target)
// ---------------------------------------------------------------------------
extern "C" void kernel_launch(void* const* d_in, const int* in_sizes, int n_in,
                              void* d_out, int out_size) {
    const float* x       = (const float*)d_in[0];
    const float* w_theta = (const float*)d_in[1];
    const float* b_theta = (const float*)d_in[2];
    const float* w_phi   = (const float*)d_in[3];
    const float* b_phi   = (const float*)d_in[4];
    const float* w_g     = (const float*)d_in[5];
    const float* b_g     = (const float*)d_in[6];
    const float* w_out   = (const float*)d_in[7];
    const float* b_out   = (const float*)d_in[8];
    const float* gamma   = (const float*)d_in[9];
    const float* beta    = (const float*)d_in[10];
    float* out = (float*)d_out;
    (void)in_sizes; (void)n_in; (void)out_size;

    float *p_tp, *p_T;
    __half* p_W2h;
    cudaGetSymbolAddress((void**)&p_tp,  d_tp);
    cudaGetSymbolAddress((void**)&p_T,   d_T);
    cudaGetSymbolAddress((void**)&p_W2h, d_W2h);

    cudaFuncSetAttribute(mma_gemm, cudaFuncAttributeMaxDynamicSharedMemorySize, GS);

    zero_stats_kernel<<<1, 256>>>();                                   // 0
    cvtxsum_kernel<<<dim3(128, 32), 256>>>(x);                          // 1
    attn_bias_kernel<<<NB, 128>>>(w_theta, b_theta, w_phi, b_phi,       // 2
                                  b_g, w_out, b_out);
    // T[n] = tp[n] @ w_g : [128,256], K=128
    sgemm_bias<64, 64, 16, 4, 4><<<dim3(4, 2, NB), 256>>>(              // 3
        p_tp, (long long)DI * DI, w_g, 0, p_T, (long long)DI * DIM, DI, DIM, DI);
    // W2h[n] = (w_out @ T[n]) * W2SCALE -> fp16 : [256,256], K=128
    sgemm_f16<64, 64, 16, 4, 4><<<dim3(4, 4, NB), 256>>>(               // 4
        w_out, 0, p_T, (long long)DI * DIM, p_W2h, (long long)DIM * DIM, DIM, DIM, DI);

    mma_gemm<<<2048, 256, GS>>>();                                      // 5  <- ncu

    finalize_kernel<<<1, 256>>>(gamma, beta);                           // 6
    out2_kernel<<<16384, 256>>>(out);                                   // 7
}